// round 8
// baseline (speedup 1.0000x reference)
#include <cuda_runtime.h>
#include <cuda_bf16.h>

#define SEQ   4096
#define NB    4
#define TOK   (NB * SEQ)
#define DIN   512
#define DH    64
#define DOUT  512
#define NCHUNK 144                      // split-j chunks per batch (Br=128)
#define SCALE_LOG2E 0.1803368801111f    // 0.125 * log2(e)

// ---------------------------------------------------------------------------
// Device scratch (allocation-free). bf16 pairs packed in u32 words along k.
// ---------------------------------------------------------------------------
__device__ unsigned g_x_hi[TOK * (DIN/2)];
__device__ unsigned g_x_lo[TOK * (DIN/2)];
__device__ unsigned g_wqkvT_hi[192 * (DIN/2)];
__device__ unsigned g_wqkvT_lo[192 * (DIN/2)];
__device__ unsigned g_woT_hi[DOUT * (DH/2)];
__device__ unsigned g_woT_lo[DOUT * (DH/2)];
__device__ unsigned g_q_hi[TOK * (DH/2)];
__device__ unsigned g_q_lo[TOK * (DH/2)];
__device__ unsigned g_k_hi[TOK * (DH/2)];
__device__ unsigned g_k_lo[TOK * (DH/2)];
__device__ unsigned short g_vT_hi[NB * DH * SEQ];   // [b][d][s]
__device__ unsigned short g_vT_lo[NB * DH * SEQ];
__device__ unsigned g_attn_hi[TOK * (DH/2)];
__device__ unsigned g_attn_lo[TOK * (DH/2)];
__device__ float g_part_o[NB * NCHUNK * 128 * 64];  // unnormalized partial O
__device__ float g_part_m[NB * NCHUNK * 128];       // log2-domain row max
__device__ float g_part_l[NB * NCHUNK * 128];       // row sum

// ---------------------------------------------------------------------------
__device__ __forceinline__ void split2(float x0, float x1, unsigned &h, unsigned &l) {
    __nv_bfloat162 hh = __floats2bfloat162_rn(x0, x1);
    h = *reinterpret_cast<unsigned*>(&hh);
    float r0 = x0 - __bfloat162float(hh.x);
    float r1 = x1 - __bfloat162float(hh.y);
    __nv_bfloat162 ll = __floats2bfloat162_rn(r0, r1);
    l = *reinterpret_cast<unsigned*>(&ll);
}
__device__ __forceinline__ void split1(float x, unsigned short &h, unsigned short &l) {
    __nv_bfloat16 hb = __float2bfloat16(x);
    h = *reinterpret_cast<unsigned short*>(&hb);
    __nv_bfloat16 lb = __float2bfloat16(x - __bfloat162float(hb));
    l = *reinterpret_cast<unsigned short*>(&lb);
}

#define MMA16816(c, a0, a1, a2, a3, b0, b1)                                   \
    asm volatile(                                                             \
        "mma.sync.aligned.m16n8k16.row.col.f32.bf16.bf16.f32 "                \
        "{%0,%1,%2,%3}, {%4,%5,%6,%7}, {%8,%9}, {%0,%1,%2,%3};\n"             \
        : "+f"((c)[0]), "+f"((c)[1]), "+f"((c)[2]), "+f"((c)[3])              \
        : "r"(a0), "r"(a1), "r"(a2), "r"(a3), "r"(b0), "r"(b1))

#define LDSM4(d0, d1, d2, d3, a)                                              \
    asm volatile("ldmatrix.sync.aligned.m8n8.x4.shared.b16 {%0,%1,%2,%3}, [%4];" \
        : "=r"(d0), "=r"(d1), "=r"(d2), "=r"(d3) : "r"(a))

__device__ __forceinline__ void cpa16(unsigned dst, const void* src) {
    asm volatile("cp.async.cg.shared.global [%0], [%1], 16;\n" :: "r"(dst), "l"(src));
}
#define CP_COMMIT asm volatile("cp.async.commit_group;\n" ::: "memory")
#define CP_WAIT0  asm volatile("cp.async.wait_group 0;\n" ::: "memory")

// ---------------------------------------------------------------------------
// Prep kernels
// ---------------------------------------------------------------------------
__global__ __launch_bounds__(256) void prep_x_kernel(const float* __restrict__ x) {
    int i0 = blockIdx.x * 1024 + threadIdx.x;
    #pragma unroll
    for (int it = 0; it < 4; it++) {
        int idx = i0 + it * 256;
        float4 v = *(const float4*)(x + (size_t)idx * 4);
        unsigned h0, l0, h1, l1;
        split2(v.x, v.y, h0, l0);
        split2(v.z, v.w, h1, l1);
        g_x_hi[2 * idx] = h0; g_x_hi[2 * idx + 1] = h1;
        g_x_lo[2 * idx] = l0; g_x_lo[2 * idx + 1] = l1;
    }
}
__global__ __launch_bounds__(256) void prep_wqkv_kernel(const float* __restrict__ w) {
    int n = blockIdx.x, kw = threadIdx.x;
    float a = w[(size_t)(2 * kw) * 192 + n];
    float b = w[(size_t)(2 * kw + 1) * 192 + n];
    unsigned h, l; split2(a, b, h, l);
    g_wqkvT_hi[n * 256 + kw] = h; g_wqkvT_lo[n * 256 + kw] = l;
}
__global__ __launch_bounds__(256) void prep_wout_kernel(const float* __restrict__ w) {
    int idx = blockIdx.x * 256 + threadIdx.x;
    int n = idx >> 5, kw = idx & 31;
    float a = w[(size_t)(2 * kw) * DOUT + n];
    float b = w[(size_t)(2 * kw + 1) * DOUT + n];
    unsigned h, l; split2(a, b, h, l);
    g_woT_hi[n * 32 + kw] = h; g_woT_lo[n * 32 + kw] = l;
}

// ---------------------------------------------------------------------------
// K1: qkv GEMM. 256 thr, tile M=128 N=64, k-chunks 32, cp.async double-buffer,
// ldmatrix fragment loads. min 3 CTAs/SM for single-wave launch.
// ---------------------------------------------------------------------------
#define QS 20

__global__ __launch_bounds__(256, 3) void qkv_mma_kernel() {
    extern __shared__ __align__(16) unsigned sq[];
    const unsigned sbase = (unsigned)__cvta_generic_to_shared(sq);
    const int t = threadIdx.x, lane = t & 31, warp = t >> 5;
    const int g = lane >> 2, tg = lane & 3;
    const int rr = lane & 7, tl = lane >> 3;
    const int m0 = blockIdx.x * 128;
    const int nb = blockIdx.y;
    const int rb = (warp & 3) * 32;
    const int cb = (warp >> 2) * 32;

    // ldmatrix per-lane byte offsets within a stage block
    const unsigned aoff = ((rb + rr + (tl & 1) * 8) * QS + (tl >> 1) * 4) * 4;
    const unsigned boff = ((cb + rr + ((tl >> 1) & 1) * 8) * QS + (tl & 1) * 4) * 4;

    auto prefetch = [&](int kc, int st) {
        unsigned sb = sbase + st * 7680 * 4;
        #pragma unroll
        for (int i = 0; i < 2; i++) {
            int idx = t + i * 256;
            int r = idx >> 2, j = (idx & 3) * 4;
            cpa16(sb + (r * QS + j) * 4,          g_x_hi + (size_t)(m0 + r) * 256 + kc * 16 + j);
            cpa16(sb + (2560 + r * QS + j) * 4,   g_x_lo + (size_t)(m0 + r) * 256 + kc * 16 + j);
        }
        {
            int r = t >> 2, j = (t & 3) * 4;
            cpa16(sb + (5120 + r * QS + j) * 4,   g_wqkvT_hi + (size_t)(nb * 64 + r) * 256 + kc * 16 + j);
            cpa16(sb + (6400 + r * QS + j) * 4,   g_wqkvT_lo + (size_t)(nb * 64 + r) * 256 + kc * 16 + j);
        }
        CP_COMMIT;
    };

    float c[2][4][4] = {};
    prefetch(0, 0);

    for (int kc = 0; kc < 16; kc++) {
        const int st = kc & 1;
        CP_WAIT0;
        __syncthreads();
        if (kc + 1 < 16) prefetch(kc + 1, st ^ 1);

        const unsigned Xb = sbase + st * 7680 * 4;

        #pragma unroll
        for (int kt = 0; kt < 2; kt++) {
            const unsigned ko = kt * 32;   // 8 words
            unsigned ah[2][4], al[2][4];
            LDSM4(ah[0][0], ah[0][1], ah[0][2], ah[0][3], Xb + aoff + ko);
            LDSM4(ah[1][0], ah[1][1], ah[1][2], ah[1][3], Xb + aoff + 16 * QS * 4 + ko);
            LDSM4(al[0][0], al[0][1], al[0][2], al[0][3], Xb + 2560 * 4 + aoff + ko);
            LDSM4(al[1][0], al[1][1], al[1][2], al[1][3], Xb + 2560 * 4 + aoff + 16 * QS * 4 + ko);
            #pragma unroll
            for (int ntp = 0; ntp < 2; ntp++) {
                unsigned bh0, bh1, bh2, bh3, bl0, bl1, bl2, bl3;
                LDSM4(bh0, bh1, bh2, bh3, Xb + 5120 * 4 + boff + ntp * 16 * QS * 4 + ko);
                LDSM4(bl0, bl1, bl2, bl3, Xb + 6400 * 4 + boff + ntp * 16 * QS * 4 + ko);
                #pragma unroll
                for (int gm = 0; gm < 2; gm++) {
                    MMA16816(c[gm][2 * ntp],     ah[gm][0], ah[gm][1], ah[gm][2], ah[gm][3], bh0, bh1);
                    MMA16816(c[gm][2 * ntp],     ah[gm][0], ah[gm][1], ah[gm][2], ah[gm][3], bl0, bl1);
                    MMA16816(c[gm][2 * ntp],     al[gm][0], al[gm][1], al[gm][2], al[gm][3], bh0, bh1);
                    MMA16816(c[gm][2 * ntp + 1], ah[gm][0], ah[gm][1], ah[gm][2], ah[gm][3], bh2, bh3);
                    MMA16816(c[gm][2 * ntp + 1], ah[gm][0], ah[gm][1], ah[gm][2], ah[gm][3], bl2, bl3);
                    MMA16816(c[gm][2 * ntp + 1], al[gm][0], al[gm][1], al[gm][2], al[gm][3], bh2, bh3);
                }
            }
        }
    }

    const float qs = (nb == 0) ? SCALE_LOG2E : 1.0f;
    if (nb < 2) {
        unsigned* oh = nb ? g_k_hi : g_q_hi;
        unsigned* ol = nb ? g_k_lo : g_q_lo;
        #pragma unroll
        for (int gm = 0; gm < 2; gm++) {
            int row = m0 + rb + 16 * gm + g;
            #pragma unroll
            for (int nt = 0; nt < 4; nt++) {
                int wd = (cb >> 1) + 4 * nt + tg;
                unsigned h, l;
                split2(c[gm][nt][0] * qs, c[gm][nt][1] * qs, h, l);
                oh[(size_t)row * 32 + wd] = h; ol[(size_t)row * 32 + wd] = l;
                split2(c[gm][nt][2] * qs, c[gm][nt][3] * qs, h, l);
                oh[(size_t)(row + 8) * 32 + wd] = h; ol[(size_t)(row + 8) * 32 + wd] = l;
            }
        }
    } else {
        const int b = (m0 + rb) >> 12;
        #pragma unroll
        for (int gm = 0; gm < 2; gm++) {
            int s = (m0 + rb + 16 * gm + g) & 4095;
            #pragma unroll
            for (int nt = 0; nt < 4; nt++) {
                #pragma unroll
                for (int e = 0; e < 4; e++) {
                    int d = cb + 8 * nt + 2 * tg + (e & 1);
                    int ss = s + (e >= 2 ? 8 : 0);
                    unsigned short h, l; split1(c[gm][nt][e], h, l);
                    size_t a = (size_t)(b * DH + d) * SEQ + ss;
                    g_vT_hi[a] = h; g_vT_lo[a] = l;
                }
            }
        }
    }
}

// ---------------------------------------------------------------------------
// K2: split-j causal flash attention. 256 thr (8 warps), Br=128, Bc=64,
// cp.async 2-stage, ldmatrix fragment loads.
// ---------------------------------------------------------------------------
#define AS 36

__global__ __launch_bounds__(256) void attn_mma_kernel() {
    extern __shared__ __align__(16) unsigned sa[];
    const unsigned sbase = (unsigned)__cvta_generic_to_shared(sa);
    const int t = threadIdx.x, lane = t & 31, warp = t >> 5;
    const int g = lane >> 2, tg = lane & 3;
    const int rr = lane & 7, tl = lane >> 3;
    const int b = blockIdx.y;
    const int cx = blockIdx.x;

    int gr = 0;
    while (cx >= 2 * (gr + 1) * (gr + 2)) gr++;
    const int u = cx - 2 * gr * (gr + 1);
    const int ib = 4 * gr + u / (gr + 1);
    const int ci = u % (gr + 1);
    const int nch = gr + 1;
    const int jbeg = ci * 8;
    const int jend = min(jbeg + 8, 2 * ib + 2);
    const int i0 = ib * 128;

    // ldmatrix per-lane byte offsets
    const unsigned aoffQ = ((16 * warp + rr + (tl & 1) * 8) * AS + (tl >> 1) * 4) * 4;
    const unsigned boffB = ((rr + ((tl >> 1) & 1) * 8) * AS + (tl & 1) * 4) * 4;

    // Q tile (plain loads; first loop sync covers visibility): 128 rows
    unsigned* Qh = sa;
    unsigned* Ql = sa + 4608;
    for (int i = t; i < 1024; i += 256) {
        int r = i >> 3, j = (i & 7) * 4;
        *(float4*)(Qh + r * AS + j) = *(const float4*)(g_q_hi + (size_t)(b * SEQ + i0 + r) * 32 + j);
        *(float4*)(Ql + r * AS + j) = *(const float4*)(g_q_lo + (size_t)(b * SEQ + i0 + r) * 32 + j);
    }

    auto prefetch = [&](int jt, int st) {
        unsigned sb = sbase + (9216 + st * 9216) * 4;
        #pragma unroll
        for (int i = 0; i < 2; i++) {
            int idx = t + i * 256;
            int r = idx >> 3, j = idx & 7;
            cpa16(sb + (r * AS + 4 * j) * 4,          g_k_hi + (size_t)(b * SEQ + jt * 64 + r) * 32 + 4 * j);
            cpa16(sb + (2304 + r * AS + 4 * j) * 4,   g_k_lo + (size_t)(b * SEQ + jt * 64 + r) * 32 + 4 * j);
            cpa16(sb + (4608 + r * AS + 4 * j) * 4,   g_vT_hi + (size_t)(b * DH + r) * SEQ + jt * 64 + 8 * j);
            cpa16(sb + (6912 + r * AS + 4 * j) * 4,   g_vT_lo + (size_t)(b * DH + r) * SEQ + jt * 64 + 8 * j);
        }
        CP_COMMIT;
    };

    float o[8][4] = {};
    float mrow[2] = {-1e30f, -1e30f};
    float lrow[2] = {0.f, 0.f};

    prefetch(jbeg, 0);

    for (int jt = jbeg; jt < jend; jt++) {
        const int st = (jt - jbeg) & 1;
        CP_WAIT0;
        __syncthreads();
        if (jt + 1 < jend) prefetch(jt + 1, st ^ 1);

        const unsigned KVb = sbase + (9216 + st * 9216) * 4;

        float c[8][4] = {};
        #pragma unroll
        for (int kt = 0; kt < 4; kt++) {
            const unsigned ko = kt * 32;
            unsigned ah0, ah1, ah2, ah3, al0, al1, al2, al3;
            LDSM4(ah0, ah1, ah2, ah3, sbase + aoffQ + ko);
            LDSM4(al0, al1, al2, al3, sbase + 4608 * 4 + aoffQ + ko);
            #pragma unroll
            for (int ntp = 0; ntp < 4; ntp++) {
                unsigned bh0, bh1, bh2, bh3, bl0, bl1, bl2, bl3;
                LDSM4(bh0, bh1, bh2, bh3, KVb + boffB + ntp * 16 * AS * 4 + ko);
                LDSM4(bl0, bl1, bl2, bl3, KVb + 2304 * 4 + boffB + ntp * 16 * AS * 4 + ko);
                MMA16816(c[2 * ntp],     ah0, ah1, ah2, ah3, bh0, bh1);
                MMA16816(c[2 * ntp],     ah0, ah1, ah2, ah3, bl0, bl1);
                MMA16816(c[2 * ntp],     al0, al1, al2, al3, bh0, bh1);
                MMA16816(c[2 * ntp + 1], ah0, ah1, ah2, ah3, bh2, bh3);
                MMA16816(c[2 * ntp + 1], ah0, ah1, ah2, ah3, bl2, bl3);
                MMA16816(c[2 * ntp + 1], al0, al1, al2, al3, bh2, bh3);
            }
        }

        if (jt >= 2 * ib) {   // partially-masked tiles (last two of the row-block)
            #pragma unroll
            for (int nt = 0; nt < 8; nt++) {
                #pragma unroll
                for (int e = 0; e < 4; e++) {
                    int row = i0 + 16 * warp + g + (e >= 2 ? 8 : 0);
                    int col = jt * 64 + 8 * nt + 2 * tg + (e & 1);
                    if (col > row) c[nt][e] = -1e30f;
                }
            }
        }

        float mx0 = -1e30f, mx1 = -1e30f;
        #pragma unroll
        for (int nt = 0; nt < 8; nt++) {
            mx0 = fmaxf(mx0, fmaxf(c[nt][0], c[nt][1]));
            mx1 = fmaxf(mx1, fmaxf(c[nt][2], c[nt][3]));
        }
        mx0 = fmaxf(mx0, __shfl_xor_sync(0xffffffffu, mx0, 1));
        mx0 = fmaxf(mx0, __shfl_xor_sync(0xffffffffu, mx0, 2));
        mx1 = fmaxf(mx1, __shfl_xor_sync(0xffffffffu, mx1, 1));
        mx1 = fmaxf(mx1, __shfl_xor_sync(0xffffffffu, mx1, 2));
        float mn0 = fmaxf(mrow[0], mx0), mn1 = fmaxf(mrow[1], mx1);
        float a0 = exp2f(mrow[0] - mn0), a1 = exp2f(mrow[1] - mn1);
        mrow[0] = mn0; mrow[1] = mn1;

        float s0 = 0.f, s1 = 0.f;
        #pragma unroll
        for (int nt = 0; nt < 8; nt++) {
            c[nt][0] = exp2f(c[nt][0] - mn0); s0 += c[nt][0];
            c[nt][1] = exp2f(c[nt][1] - mn0); s0 += c[nt][1];
            c[nt][2] = exp2f(c[nt][2] - mn1); s1 += c[nt][2];
            c[nt][3] = exp2f(c[nt][3] - mn1); s1 += c[nt][3];
        }
        s0 += __shfl_xor_sync(0xffffffffu, s0, 1);
        s0 += __shfl_xor_sync(0xffffffffu, s0, 2);
        s1 += __shfl_xor_sync(0xffffffffu, s1, 1);
        s1 += __shfl_xor_sync(0xffffffffu, s1, 2);
        lrow[0] = lrow[0] * a0 + s0;
        lrow[1] = lrow[1] * a1 + s1;
        #pragma unroll
        for (int nt = 0; nt < 8; nt++) {
            o[nt][0] *= a0; o[nt][1] *= a0; o[nt][2] *= a1; o[nt][3] *= a1;
        }

        #pragma unroll
        for (int kt = 0; kt < 4; kt++) {
            unsigned ah0, al0, ah1, al1, ah2, al2, ah3, al3;
            split2(c[2 * kt][0],     c[2 * kt][1],     ah0, al0);
            split2(c[2 * kt][2],     c[2 * kt][3],     ah1, al1);
            split2(c[2 * kt + 1][0], c[2 * kt + 1][1], ah2, al2);
            split2(c[2 * kt + 1][2], c[2 * kt + 1][3], ah3, al3);
            const unsigned ko = kt * 32;
            #pragma unroll
            for (int ntp = 0; ntp < 4; ntp++) {
                unsigned bh0, bh1, bh2, bh3, bl0, bl1, bl2, bl3;
                LDSM4(bh0, bh1, bh2, bh3, KVb + 4608 * 4 + boffB + ntp * 16 * AS * 4 + ko);
                LDSM4(bl0, bl1, bl2, bl3, KVb + 6912 * 4 + boffB + ntp * 16 * AS * 4 + ko);
                MMA16816(o[2 * ntp],     ah0, ah1, ah2, ah3, bh0, bh1);
                MMA16816(o[2 * ntp],     ah0, ah1, ah2, ah3, bl0, bl1);
                MMA16816(o[2 * ntp],     al0, al1, al2, al3, bh0, bh1);
                MMA16816(o[2 * ntp + 1], ah0, ah1, ah2, ah3, bh2, bh3);
                MMA16816(o[2 * ntp + 1], ah0, ah1, ah2, ah3, bl2, bl3);
                MMA16816(o[2 * ntp + 1], al0, al1, al2, al3, bh2, bh3);
            }
        }
    }

    if (nch == 1) {
        float inv0 = 1.0f / lrow[0], inv1 = 1.0f / lrow[1];
        const int tok = b * SEQ + i0 + 16 * warp + g;
        #pragma unroll
        for (int nt = 0; nt < 8; nt++) {
            unsigned h, l;
            split2(o[nt][0] * inv0, o[nt][1] * inv0, h, l);
            g_attn_hi[(size_t)tok * 32 + 4 * nt + tg] = h;
            g_attn_lo[(size_t)tok * 32 + 4 * nt + tg] = l;
            split2(o[nt][2] * inv1, o[nt][3] * inv1, h, l);
            g_attn_hi[(size_t)(tok + 8) * 32 + 4 * nt + tg] = h;
            g_attn_lo[(size_t)(tok + 8) * 32 + 4 * nt + tg] = l;
        }
    } else {
        const int pb = b * NCHUNK + cx;
        const int r0 = 16 * warp + g;
        #pragma unroll
        for (int nt = 0; nt < 8; nt++) {
            int col = 8 * nt + 2 * tg;
            *(float2*)&g_part_o[((size_t)pb * 128 + r0) * 64 + col]     = make_float2(o[nt][0], o[nt][1]);
            *(float2*)&g_part_o[((size_t)pb * 128 + r0 + 8) * 64 + col] = make_float2(o[nt][2], o[nt][3]);
        }
        if (tg == 0) {
            g_part_m[pb * 128 + r0] = mrow[0];     g_part_l[pb * 128 + r0] = lrow[0];
            g_part_m[pb * 128 + r0 + 8] = mrow[1]; g_part_l[pb * 128 + r0 + 8] = lrow[1];
        }
    }
}

// ---------------------------------------------------------------------------
// K2b: merge split-j partials (row blocks ib >= 4; up to 8 chunks each)
// ---------------------------------------------------------------------------
__global__ __launch_bounds__(256) void merge_kernel() {
    const int ib = 4 + blockIdx.x;   // 4..31
    const int b = blockIdx.y;
    const int gr = ib >> 2;
    const int nch = gr + 1;
    const int cx0 = 2 * gr * (gr + 1) + (ib - 4 * gr) * (gr + 1);

    const int t = threadIdx.x;
    const int r = t >> 1, half = t & 1;   // r in 0..127

    float mc[8], lc[8], wv[8];
    float mstar = -1e30f;
    for (int c = 0; c < nch; c++) {
        mc[c] = g_part_m[(b * NCHUNK + cx0 + c) * 128 + r];
        lc[c] = g_part_l[(b * NCHUNK + cx0 + c) * 128 + r];
        mstar = fmaxf(mstar, mc[c]);
    }
    float lsum = 0.f;
    for (int c = 0; c < nch; c++) { wv[c] = exp2f(mc[c] - mstar); lsum += wv[c] * lc[c]; }
    const float inv = 1.0f / lsum;

    const int tok = b * SEQ + ib * 128 + r;
    #pragma unroll 4
    for (int j = 0; j < 16; j++) {
        int col = half * 32 + 2 * j;
        float a0 = 0.f, a1 = 0.f;
        for (int c = 0; c < nch; c++) {
            float2 v = *(const float2*)&g_part_o[((size_t)(b * NCHUNK + cx0 + c) * 128 + r) * 64 + col];
            a0 += wv[c] * v.x; a1 += wv[c] * v.y;
        }
        unsigned h, l; split2(a0 * inv, a1 * inv, h, l);
        g_attn_hi[(size_t)tok * 32 + half * 16 + j] = h;
        g_attn_lo[(size_t)tok * 32 + half * 16 + j] = l;
    }
}

// ---------------------------------------------------------------------------
// K3: out = attn @ W_out + b_out. 256 thr, tile 128x128, ldmatrix loads.
// min 3 CTAs/SM.
// ---------------------------------------------------------------------------
__global__ __launch_bounds__(256, 3) void out_mma_kernel(
    const float* __restrict__ bias, float* __restrict__ out)
{
    extern __shared__ __align__(16) unsigned so[];
    unsigned* Ah = so;
    unsigned* Al = so + 4608;
    unsigned* Bh = so + 9216;
    unsigned* Bl = so + 13824;

    const unsigned sbase = (unsigned)__cvta_generic_to_shared(so);
    const int t = threadIdx.x, lane = t & 31, warp = t >> 5;
    const int g = lane >> 2, tg = lane & 3;
    const int rr = lane & 7, tl = lane >> 3;
    const int m0 = blockIdx.x * 128;
    const int n0 = blockIdx.y * 128;
    const int rb = (warp & 3) * 32;
    const int cbn = (warp >> 2) * 64;

    const unsigned aoff = ((rb + rr + (tl & 1) * 8) * AS + (tl >> 1) * 4) * 4;
    const unsigned boff = ((cbn + rr + ((tl >> 1) & 1) * 8) * AS + (tl & 1) * 4) * 4;

    for (int i = t; i < 1024; i += 256) {
        int r = i >> 3, j = (i & 7) * 4;
        *(float4*)(Ah + r * AS + j) = *(const float4*)(g_attn_hi + (size_t)(m0 + r) * 32 + j);
        *(float4*)(Al + r * AS + j) = *(const float4*)(g_attn_lo + (size_t)(m0 + r) * 32 + j);
        *(float4*)(Bh + r * AS + j) = *(const float4*)(g_woT_hi + (size_t)(n0 + r) * 32 + j);
        *(float4*)(Bl + r * AS + j) = *(const float4*)(g_woT_lo + (size_t)(n0 + r) * 32 + j);
    }
    __syncthreads();

    float c[2][8][4] = {};
    #pragma unroll
    for (int kt = 0; kt < 4; kt++) {
        const unsigned ko = kt * 32;
        unsigned ah[2][4], al[2][4];
        LDSM4(ah[0][0], ah[0][1], ah[0][2], ah[0][3], sbase + aoff + ko);
        LDSM4(ah[1][0], ah[1][1], ah[1][2], ah[1][3], sbase + aoff + 16 * AS * 4 + ko);
        LDSM4(al[0][0], al[0][1], al[0][2], al[0][3], sbase + 4608 * 4 + aoff + ko);
        LDSM4(al[1][0], al[1][1], al[1][2], al[1][3], sbase + 4608 * 4 + aoff + 16 * AS * 4 + ko);
        #pragma unroll
        for (int ntp = 0; ntp < 4; ntp++) {
            unsigned bh0, bh1, bh2, bh3, bl0, bl1, bl2, bl3;
            LDSM4(bh0, bh1, bh2, bh3, sbase + 9216 * 4 + boff + ntp * 16 * AS * 4 + ko);
            LDSM4(bl0, bl1, bl2, bl3, sbase + 13824 * 4 + boff + ntp * 16 * AS * 4 + ko);
            #pragma unroll
            for (int gm = 0; gm < 2; gm++) {
                MMA16816(c[gm][2 * ntp],     ah[gm][0], ah[gm][1], ah[gm][2], ah[gm][3], bh0, bh1);
                MMA16816(c[gm][2 * ntp],     ah[gm][0], ah[gm][1], ah[gm][2], ah[gm][3], bl0, bl1);
                MMA16816(c[gm][2 * ntp],     al[gm][0], al[gm][1], al[gm][2], al[gm][3], bh0, bh1);
                MMA16816(c[gm][2 * ntp + 1], ah[gm][0], ah[gm][1], ah[gm][2], ah[gm][3], bh2, bh3);
                MMA16816(c[gm][2 * ntp + 1], ah[gm][0], ah[gm][1], ah[gm][2], ah[gm][3], bl2, bl3);
                MMA16816(c[gm][2 * ntp + 1], al[gm][0], al[gm][1], al[gm][2], al[gm][3], bh2, bh3);
            }
        }
    }

    #pragma unroll
    for (int gm = 0; gm < 2; gm++) {
        int row = m0 + rb + 16 * gm + g;
        #pragma unroll
        for (int nt = 0; nt < 8; nt++) {
            int col = n0 + cbn + 8 * nt + 2 * tg;
            float b0 = bias[col], b1 = bias[col + 1];
            *(float2*)(out + (size_t)row * DOUT + col)       = make_float2(c[gm][nt][0] + b0, c[gm][nt][1] + b1);
            *(float2*)(out + (size_t)(row + 8) * DOUT + col) = make_float2(c[gm][nt][2] + b0, c[gm][nt][3] + b1);
        }
    }
}

// ---------------------------------------------------------------------------
extern "C" void kernel_launch(void* const* d_in, const int* in_sizes, int n_in,
                              void* d_out, int out_size)
{
    const float* x    = (const float*)d_in[0];
    const float* Wqkv = (const float*)d_in[1];
    const float* Wout = (const float*)d_in[2];
    const float* bout = (const float*)d_in[3];
    float* out = (float*)d_out;

    prep_x_kernel<<<2048, 256>>>(x);
    prep_wqkv_kernel<<<192, 256>>>(Wqkv);
    prep_wout_kernel<<<64, 256>>>(Wout);

    cudaFuncSetAttribute(qkv_mma_kernel, cudaFuncAttributeMaxDynamicSharedMemorySize, 61440);
    qkv_mma_kernel<<<dim3(TOK / 128, 3), 256, 61440>>>();

    cudaFuncSetAttribute(attn_mma_kernel, cudaFuncAttributeMaxDynamicSharedMemorySize, 110592);
    attn_mma_kernel<<<dim3(NCHUNK, NB), 256, 110592>>>();

    merge_kernel<<<dim3(28, NB), 256>>>();

    cudaFuncSetAttribute(out_mma_kernel, cudaFuncAttributeMaxDynamicSharedMemorySize, 73728);
    out_mma_kernel<<<dim3(TOK / 128, DOUT / 128), 256, 73728>>>(bout, out);
}

// round 9
// speedup vs baseline: 1.0373x; 1.0373x over previous
#include <cuda_runtime.h>
#include <cuda_bf16.h>

#define SEQ   4096
#define NB    4
#define TOK   (NB * SEQ)
#define DIN   512
#define DH    64
#define DOUT  512
#define NCHUNK 144                      // split-j chunks per batch (Br=128)
#define SCALE_LOG2E 0.1803368801111f    // 0.125 * log2(e)

// ---------------------------------------------------------------------------
// Device scratch (allocation-free). bf16 pairs packed in u32 words along k.
// ---------------------------------------------------------------------------
__device__ unsigned g_x_hi[TOK * (DIN/2)];
__device__ unsigned g_x_lo[TOK * (DIN/2)];
__device__ unsigned g_wqkvT_hi[192 * (DIN/2)];
__device__ unsigned g_wqkvT_lo[192 * (DIN/2)];
__device__ unsigned g_woT_hi[DOUT * (DH/2)];
__device__ unsigned g_woT_lo[DOUT * (DH/2)];
__device__ unsigned g_q_hi[TOK * (DH/2)];
__device__ unsigned g_q_lo[TOK * (DH/2)];
__device__ unsigned g_k_hi[TOK * (DH/2)];
__device__ unsigned g_k_lo[TOK * (DH/2)];
__device__ unsigned short g_vT_hi[NB * DH * SEQ];   // [b][d][s]
__device__ unsigned short g_vT_lo[NB * DH * SEQ];
__device__ unsigned g_attn_hi[TOK * (DH/2)];
__device__ unsigned g_attn_lo[TOK * (DH/2)];
__device__ float g_part_o[NB * NCHUNK * 128 * 64];  // unnormalized partial O
__device__ float g_part_m[NB * NCHUNK * 128];       // log2-domain row max
__device__ float g_part_l[NB * NCHUNK * 128];       // row sum

// ---------------------------------------------------------------------------
__device__ __forceinline__ void split2(float x0, float x1, unsigned &h, unsigned &l) {
    __nv_bfloat162 hh = __floats2bfloat162_rn(x0, x1);
    h = *reinterpret_cast<unsigned*>(&hh);
    float r0 = x0 - __bfloat162float(hh.x);
    float r1 = x1 - __bfloat162float(hh.y);
    __nv_bfloat162 ll = __floats2bfloat162_rn(r0, r1);
    l = *reinterpret_cast<unsigned*>(&ll);
}
__device__ __forceinline__ void split1(float x, unsigned short &h, unsigned short &l) {
    __nv_bfloat16 hb = __float2bfloat16(x);
    h = *reinterpret_cast<unsigned short*>(&hb);
    __nv_bfloat16 lb = __float2bfloat16(x - __bfloat162float(hb));
    l = *reinterpret_cast<unsigned short*>(&lb);
}

#define MMA16816(c, a0, a1, a2, a3, b0, b1)                                   \
    asm volatile(                                                             \
        "mma.sync.aligned.m16n8k16.row.col.f32.bf16.bf16.f32 "                \
        "{%0,%1,%2,%3}, {%4,%5,%6,%7}, {%8,%9}, {%0,%1,%2,%3};\n"             \
        : "+f"((c)[0]), "+f"((c)[1]), "+f"((c)[2]), "+f"((c)[3])              \
        : "r"(a0), "r"(a1), "r"(a2), "r"(a3), "r"(b0), "r"(b1))

#define LDSM4(d0, d1, d2, d3, a)                                              \
    asm volatile("ldmatrix.sync.aligned.m8n8.x4.shared.b16 {%0,%1,%2,%3}, [%4];" \
        : "=r"(d0), "=r"(d1), "=r"(d2), "=r"(d3) : "r"(a))

__device__ __forceinline__ void cpa16(unsigned dst, const void* src) {
    asm volatile("cp.async.cg.shared.global [%0], [%1], 16;\n" :: "r"(dst), "l"(src));
}
#define CP_COMMIT asm volatile("cp.async.commit_group;\n" ::: "memory")
#define CP_WAIT0  asm volatile("cp.async.wait_group 0;\n" ::: "memory")

// ---------------------------------------------------------------------------
// Prep kernels
// ---------------------------------------------------------------------------
__global__ __launch_bounds__(256) void prep_x_kernel(const float* __restrict__ x) {
    int i0 = blockIdx.x * 1024 + threadIdx.x;
    #pragma unroll
    for (int it = 0; it < 4; it++) {
        int idx = i0 + it * 256;
        float4 v = *(const float4*)(x + (size_t)idx * 4);
        unsigned h0, l0, h1, l1;
        split2(v.x, v.y, h0, l0);
        split2(v.z, v.w, h1, l1);
        g_x_hi[2 * idx] = h0; g_x_hi[2 * idx + 1] = h1;
        g_x_lo[2 * idx] = l0; g_x_lo[2 * idx + 1] = l1;
    }
}
__global__ __launch_bounds__(256) void prep_wqkv_kernel(const float* __restrict__ w) {
    int n = blockIdx.x, kw = threadIdx.x;
    float a = w[(size_t)(2 * kw) * 192 + n];
    float b = w[(size_t)(2 * kw + 1) * 192 + n];
    unsigned h, l; split2(a, b, h, l);
    g_wqkvT_hi[n * 256 + kw] = h; g_wqkvT_lo[n * 256 + kw] = l;
}
__global__ __launch_bounds__(256) void prep_wout_kernel(const float* __restrict__ w) {
    int idx = blockIdx.x * 256 + threadIdx.x;
    int n = idx >> 5, kw = idx & 31;
    float a = w[(size_t)(2 * kw) * DOUT + n];
    float b = w[(size_t)(2 * kw + 1) * DOUT + n];
    unsigned h, l; split2(a, b, h, l);
    g_woT_hi[n * 32 + kw] = h; g_woT_lo[n * 32 + kw] = l;
}

// ---------------------------------------------------------------------------
// K1: qkv GEMM, single-wave fat tile. 512 thr (16 warps: 4m x 4n), CTA tile
// M=128 x N=192 (all of q|k|v), k-chunks 32, cp.async double-buffer, ldmatrix.
// grid = 128 CTAs = one wave on 148 SMs. X read once (not 3x).
// smem words per stage (12800): XH 0, XL 2560, WH 5120, WL 8960.
// ---------------------------------------------------------------------------
#define QS 20

__global__ __launch_bounds__(512) void qkv_mma_kernel() {
    extern __shared__ __align__(16) unsigned sq[];
    const unsigned sbase = (unsigned)__cvta_generic_to_shared(sq);
    const int t = threadIdx.x, lane = t & 31, warp = t >> 5;
    const int g = lane >> 2, tg = lane & 3;
    const int rr = lane & 7, tl = lane >> 3;
    const int m0 = blockIdx.x * 128;
    const int rb = (warp & 3) * 32;    // m-warp: 32 rows
    const int cb = (warp >> 2) * 48;   // n-warp: 48 cols

    // ldmatrix per-lane byte offsets within a stage block
    const unsigned aoff = ((rb + rr + (tl & 1) * 8) * QS + (tl >> 1) * 4) * 4;
    const unsigned boff = ((cb + rr + ((tl >> 1) & 1) * 8) * QS + (tl & 1) * 4) * 4;

    auto prefetch = [&](int kc, int st) {
        unsigned sb = sbase + st * 12800 * 4;
        {   // X hi/lo: 512 float4 each, 1 per thread
            int r = t >> 2, j = (t & 3) * 4;
            cpa16(sb + (r * QS + j) * 4,          g_x_hi + (size_t)(m0 + r) * 256 + kc * 16 + j);
            cpa16(sb + (2560 + r * QS + j) * 4,   g_x_lo + (size_t)(m0 + r) * 256 + kc * 16 + j);
        }
        // W hi/lo: 768 float4 each
        #pragma unroll
        for (int i = 0; i < 2; i++) {
            int idx = t + i * 512;
            if (idx < 768) {
                int r = idx >> 2, j = (idx & 3) * 4;
                cpa16(sb + (5120 + r * QS + j) * 4,   g_wqkvT_hi + (size_t)r * 256 + kc * 16 + j);
                cpa16(sb + (8960 + r * QS + j) * 4,   g_wqkvT_lo + (size_t)r * 256 + kc * 16 + j);
            }
        }
        CP_COMMIT;
    };

    float c[2][6][4] = {};
    prefetch(0, 0);

    for (int kc = 0; kc < 16; kc++) {
        const int st = kc & 1;
        CP_WAIT0;
        __syncthreads();
        if (kc + 1 < 16) prefetch(kc + 1, st ^ 1);

        const unsigned Xb = sbase + st * 12800 * 4;

        #pragma unroll
        for (int kt = 0; kt < 2; kt++) {
            const unsigned ko = kt * 32;   // 8 words
            unsigned ah[2][4], al[2][4];
            LDSM4(ah[0][0], ah[0][1], ah[0][2], ah[0][3], Xb + aoff + ko);
            LDSM4(ah[1][0], ah[1][1], ah[1][2], ah[1][3], Xb + aoff + 16 * QS * 4 + ko);
            LDSM4(al[0][0], al[0][1], al[0][2], al[0][3], Xb + 2560 * 4 + aoff + ko);
            LDSM4(al[1][0], al[1][1], al[1][2], al[1][3], Xb + 2560 * 4 + aoff + 16 * QS * 4 + ko);
            #pragma unroll
            for (int ntp = 0; ntp < 3; ntp++) {
                unsigned bh0, bh1, bh2, bh3, bl0, bl1, bl2, bl3;
                LDSM4(bh0, bh1, bh2, bh3, Xb + 5120 * 4 + boff + ntp * 16 * QS * 4 + ko);
                LDSM4(bl0, bl1, bl2, bl3, Xb + 8960 * 4 + boff + ntp * 16 * QS * 4 + ko);
                #pragma unroll
                for (int gm = 0; gm < 2; gm++) {
                    MMA16816(c[gm][2 * ntp],     ah[gm][0], ah[gm][1], ah[gm][2], ah[gm][3], bh0, bh1);
                    MMA16816(c[gm][2 * ntp],     ah[gm][0], ah[gm][1], ah[gm][2], ah[gm][3], bl0, bl1);
                    MMA16816(c[gm][2 * ntp],     al[gm][0], al[gm][1], al[gm][2], al[gm][3], bh0, bh1);
                    MMA16816(c[gm][2 * ntp + 1], ah[gm][0], ah[gm][1], ah[gm][2], ah[gm][3], bh2, bh3);
                    MMA16816(c[gm][2 * ntp + 1], ah[gm][0], ah[gm][1], ah[gm][2], ah[gm][3], bl2, bl3);
                    MMA16816(c[gm][2 * ntp + 1], al[gm][0], al[gm][1], al[gm][2], al[gm][3], bh2, bh3);
                }
            }
        }
    }

    // Epilogue: each n8 tile lies wholly in Q ([0,64)), K ([64,128)) or V ([128,192)).
    #pragma unroll
    for (int gm = 0; gm < 2; gm++) {
        int row = m0 + rb + 16 * gm + g;
        #pragma unroll
        for (int nt = 0; nt < 6; nt++) {
            int gcol = cb + 8 * nt;
            if (gcol < 128) {   // Q or K
                const bool isQ = (gcol < 64);
                unsigned* oh = isQ ? g_q_hi : g_k_hi;
                unsigned* ol = isQ ? g_q_lo : g_k_lo;
                const float qs = isQ ? SCALE_LOG2E : 1.0f;
                int wd = ((gcol & 63) >> 1) + tg;
                unsigned h, l;
                split2(c[gm][nt][0] * qs, c[gm][nt][1] * qs, h, l);
                oh[(size_t)row * 32 + wd] = h; ol[(size_t)row * 32 + wd] = l;
                split2(c[gm][nt][2] * qs, c[gm][nt][3] * qs, h, l);
                oh[(size_t)(row + 8) * 32 + wd] = h; ol[(size_t)(row + 8) * 32 + wd] = l;
            } else {            // V: transposed split store
                const int b = row >> 12;
                const int s = row & 4095;
                #pragma unroll
                for (int e = 0; e < 4; e++) {
                    int d = (gcol - 128) + 2 * tg + (e & 1);
                    int ss = s + (e >= 2 ? 8 : 0);
                    unsigned short h, l; split1(c[gm][nt][e], h, l);
                    size_t a = (size_t)(b * DH + d) * SEQ + ss;
                    g_vT_hi[a] = h; g_vT_lo[a] = l;
                }
            }
        }
    }
}

// ---------------------------------------------------------------------------
// K2: split-j causal flash attention. 256 thr (8 warps), Br=128, Bc=64,
// cp.async 2-stage, ldmatrix fragment loads.
// ---------------------------------------------------------------------------
#define AS 36

__global__ __launch_bounds__(256) void attn_mma_kernel() {
    extern __shared__ __align__(16) unsigned sa[];
    const unsigned sbase = (unsigned)__cvta_generic_to_shared(sa);
    const int t = threadIdx.x, lane = t & 31, warp = t >> 5;
    const int g = lane >> 2, tg = lane & 3;
    const int rr = lane & 7, tl = lane >> 3;
    const int b = blockIdx.y;
    const int cx = blockIdx.x;

    int gr = 0;
    while (cx >= 2 * (gr + 1) * (gr + 2)) gr++;
    const int u = cx - 2 * gr * (gr + 1);
    const int ib = 4 * gr + u / (gr + 1);
    const int ci = u % (gr + 1);
    const int nch = gr + 1;
    const int jbeg = ci * 8;
    const int jend = min(jbeg + 8, 2 * ib + 2);
    const int i0 = ib * 128;

    // ldmatrix per-lane byte offsets
    const unsigned aoffQ = ((16 * warp + rr + (tl & 1) * 8) * AS + (tl >> 1) * 4) * 4;
    const unsigned boffB = ((rr + ((tl >> 1) & 1) * 8) * AS + (tl & 1) * 4) * 4;

    // Q tile (plain loads; first loop sync covers visibility): 128 rows
    unsigned* Qh = sa;
    unsigned* Ql = sa + 4608;
    for (int i = t; i < 1024; i += 256) {
        int r = i >> 3, j = (i & 7) * 4;
        *(float4*)(Qh + r * AS + j) = *(const float4*)(g_q_hi + (size_t)(b * SEQ + i0 + r) * 32 + j);
        *(float4*)(Ql + r * AS + j) = *(const float4*)(g_q_lo + (size_t)(b * SEQ + i0 + r) * 32 + j);
    }

    auto prefetch = [&](int jt, int st) {
        unsigned sb = sbase + (9216 + st * 9216) * 4;
        #pragma unroll
        for (int i = 0; i < 2; i++) {
            int idx = t + i * 256;
            int r = idx >> 3, j = idx & 7;
            cpa16(sb + (r * AS + 4 * j) * 4,          g_k_hi + (size_t)(b * SEQ + jt * 64 + r) * 32 + 4 * j);
            cpa16(sb + (2304 + r * AS + 4 * j) * 4,   g_k_lo + (size_t)(b * SEQ + jt * 64 + r) * 32 + 4 * j);
            cpa16(sb + (4608 + r * AS + 4 * j) * 4,   g_vT_hi + (size_t)(b * DH + r) * SEQ + jt * 64 + 8 * j);
            cpa16(sb + (6912 + r * AS + 4 * j) * 4,   g_vT_lo + (size_t)(b * DH + r) * SEQ + jt * 64 + 8 * j);
        }
        CP_COMMIT;
    };

    float o[8][4] = {};
    float mrow[2] = {-1e30f, -1e30f};
    float lrow[2] = {0.f, 0.f};

    prefetch(jbeg, 0);

    for (int jt = jbeg; jt < jend; jt++) {
        const int st = (jt - jbeg) & 1;
        CP_WAIT0;
        __syncthreads();
        if (jt + 1 < jend) prefetch(jt + 1, st ^ 1);

        const unsigned KVb = sbase + (9216 + st * 9216) * 4;

        float c[8][4] = {};
        #pragma unroll
        for (int kt = 0; kt < 4; kt++) {
            const unsigned ko = kt * 32;
            unsigned ah0, ah1, ah2, ah3, al0, al1, al2, al3;
            LDSM4(ah0, ah1, ah2, ah3, sbase + aoffQ + ko);
            LDSM4(al0, al1, al2, al3, sbase + 4608 * 4 + aoffQ + ko);
            #pragma unroll
            for (int ntp = 0; ntp < 4; ntp++) {
                unsigned bh0, bh1, bh2, bh3, bl0, bl1, bl2, bl3;
                LDSM4(bh0, bh1, bh2, bh3, KVb + boffB + ntp * 16 * AS * 4 + ko);
                LDSM4(bl0, bl1, bl2, bl3, KVb + 2304 * 4 + boffB + ntp * 16 * AS * 4 + ko);
                MMA16816(c[2 * ntp],     ah0, ah1, ah2, ah3, bh0, bh1);
                MMA16816(c[2 * ntp],     ah0, ah1, ah2, ah3, bl0, bl1);
                MMA16816(c[2 * ntp],     al0, al1, al2, al3, bh0, bh1);
                MMA16816(c[2 * ntp + 1], ah0, ah1, ah2, ah3, bh2, bh3);
                MMA16816(c[2 * ntp + 1], ah0, ah1, ah2, ah3, bl2, bl3);
                MMA16816(c[2 * ntp + 1], al0, al1, al2, al3, bh2, bh3);
            }
        }

        if (jt >= 2 * ib) {   // partially-masked tiles (last two of the row-block)
            #pragma unroll
            for (int nt = 0; nt < 8; nt++) {
                #pragma unroll
                for (int e = 0; e < 4; e++) {
                    int row = i0 + 16 * warp + g + (e >= 2 ? 8 : 0);
                    int col = jt * 64 + 8 * nt + 2 * tg + (e & 1);
                    if (col > row) c[nt][e] = -1e30f;
                }
            }
        }

        float mx0 = -1e30f, mx1 = -1e30f;
        #pragma unroll
        for (int nt = 0; nt < 8; nt++) {
            mx0 = fmaxf(mx0, fmaxf(c[nt][0], c[nt][1]));
            mx1 = fmaxf(mx1, fmaxf(c[nt][2], c[nt][3]));
        }
        mx0 = fmaxf(mx0, __shfl_xor_sync(0xffffffffu, mx0, 1));
        mx0 = fmaxf(mx0, __shfl_xor_sync(0xffffffffu, mx0, 2));
        mx1 = fmaxf(mx1, __shfl_xor_sync(0xffffffffu, mx1, 1));
        mx1 = fmaxf(mx1, __shfl_xor_sync(0xffffffffu, mx1, 2));
        float mn0 = fmaxf(mrow[0], mx0), mn1 = fmaxf(mrow[1], mx1);
        float a0 = exp2f(mrow[0] - mn0), a1 = exp2f(mrow[1] - mn1);
        mrow[0] = mn0; mrow[1] = mn1;

        float s0 = 0.f, s1 = 0.f;
        #pragma unroll
        for (int nt = 0; nt < 8; nt++) {
            c[nt][0] = exp2f(c[nt][0] - mn0); s0 += c[nt][0];
            c[nt][1] = exp2f(c[nt][1] - mn0); s0 += c[nt][1];
            c[nt][2] = exp2f(c[nt][2] - mn1); s1 += c[nt][2];
            c[nt][3] = exp2f(c[nt][3] - mn1); s1 += c[nt][3];
        }
        s0 += __shfl_xor_sync(0xffffffffu, s0, 1);
        s0 += __shfl_xor_sync(0xffffffffu, s0, 2);
        s1 += __shfl_xor_sync(0xffffffffu, s1, 1);
        s1 += __shfl_xor_sync(0xffffffffu, s1, 2);
        lrow[0] = lrow[0] * a0 + s0;
        lrow[1] = lrow[1] * a1 + s1;
        #pragma unroll
        for (int nt = 0; nt < 8; nt++) {
            o[nt][0] *= a0; o[nt][1] *= a0; o[nt][2] *= a1; o[nt][3] *= a1;
        }

        #pragma unroll
        for (int kt = 0; kt < 4; kt++) {
            unsigned ah0, al0, ah1, al1, ah2, al2, ah3, al3;
            split2(c[2 * kt][0],     c[2 * kt][1],     ah0, al0);
            split2(c[2 * kt][2],     c[2 * kt][3],     ah1, al1);
            split2(c[2 * kt + 1][0], c[2 * kt + 1][1], ah2, al2);
            split2(c[2 * kt + 1][2], c[2 * kt + 1][3], ah3, al3);
            const unsigned ko = kt * 32;
            #pragma unroll
            for (int ntp = 0; ntp < 4; ntp++) {
                unsigned bh0, bh1, bh2, bh3, bl0, bl1, bl2, bl3;
                LDSM4(bh0, bh1, bh2, bh3, KVb + 4608 * 4 + boffB + ntp * 16 * AS * 4 + ko);
                LDSM4(bl0, bl1, bl2, bl3, KVb + 6912 * 4 + boffB + ntp * 16 * AS * 4 + ko);
                MMA16816(o[2 * ntp],     ah0, ah1, ah2, ah3, bh0, bh1);
                MMA16816(o[2 * ntp],     ah0, ah1, ah2, ah3, bl0, bl1);
                MMA16816(o[2 * ntp],     al0, al1, al2, al3, bh0, bh1);
                MMA16816(o[2 * ntp + 1], ah0, ah1, ah2, ah3, bh2, bh3);
                MMA16816(o[2 * ntp + 1], ah0, ah1, ah2, ah3, bl2, bl3);
                MMA16816(o[2 * ntp + 1], al0, al1, al2, al3, bh2, bh3);
            }
        }
    }

    if (nch == 1) {
        float inv0 = 1.0f / lrow[0], inv1 = 1.0f / lrow[1];
        const int tok = b * SEQ + i0 + 16 * warp + g;
        #pragma unroll
        for (int nt = 0; nt < 8; nt++) {
            unsigned h, l;
            split2(o[nt][0] * inv0, o[nt][1] * inv0, h, l);
            g_attn_hi[(size_t)tok * 32 + 4 * nt + tg] = h;
            g_attn_lo[(size_t)tok * 32 + 4 * nt + tg] = l;
            split2(o[nt][2] * inv1, o[nt][3] * inv1, h, l);
            g_attn_hi[(size_t)(tok + 8) * 32 + 4 * nt + tg] = h;
            g_attn_lo[(size_t)(tok + 8) * 32 + 4 * nt + tg] = l;
        }
    } else {
        const int pb = b * NCHUNK + cx;
        const int r0 = 16 * warp + g;
        #pragma unroll
        for (int nt = 0; nt < 8; nt++) {
            int col = 8 * nt + 2 * tg;
            *(float2*)&g_part_o[((size_t)pb * 128 + r0) * 64 + col]     = make_float2(o[nt][0], o[nt][1]);
            *(float2*)&g_part_o[((size_t)pb * 128 + r0 + 8) * 64 + col] = make_float2(o[nt][2], o[nt][3]);
        }
        if (tg == 0) {
            g_part_m[pb * 128 + r0] = mrow[0];     g_part_l[pb * 128 + r0] = lrow[0];
            g_part_m[pb * 128 + r0 + 8] = mrow[1]; g_part_l[pb * 128 + r0 + 8] = lrow[1];
        }
    }
}

// ---------------------------------------------------------------------------
// K2b: merge split-j partials (row blocks ib >= 4; up to 8 chunks each)
// ---------------------------------------------------------------------------
__global__ __launch_bounds__(256) void merge_kernel() {
    const int ib = 4 + blockIdx.x;   // 4..31
    const int b = blockIdx.y;
    const int gr = ib >> 2;
    const int nch = gr + 1;
    const int cx0 = 2 * gr * (gr + 1) + (ib - 4 * gr) * (gr + 1);

    const int t = threadIdx.x;
    const int r = t >> 1, half = t & 1;   // r in 0..127

    float mc[8], lc[8], wv[8];
    float mstar = -1e30f;
    for (int c = 0; c < nch; c++) {
        mc[c] = g_part_m[(b * NCHUNK + cx0 + c) * 128 + r];
        lc[c] = g_part_l[(b * NCHUNK + cx0 + c) * 128 + r];
        mstar = fmaxf(mstar, mc[c]);
    }
    float lsum = 0.f;
    for (int c = 0; c < nch; c++) { wv[c] = exp2f(mc[c] - mstar); lsum += wv[c] * lc[c]; }
    const float inv = 1.0f / lsum;

    const int tok = b * SEQ + ib * 128 + r;
    #pragma unroll 4
    for (int j = 0; j < 16; j++) {
        int col = half * 32 + 2 * j;
        float a0 = 0.f, a1 = 0.f;
        for (int c = 0; c < nch; c++) {
            float2 v = *(const float2*)&g_part_o[((size_t)(b * NCHUNK + cx0 + c) * 128 + r) * 64 + col];
            a0 += wv[c] * v.x; a1 += wv[c] * v.y;
        }
        unsigned h, l; split2(a0 * inv, a1 * inv, h, l);
        g_attn_hi[(size_t)tok * 32 + half * 16 + j] = h;
        g_attn_lo[(size_t)tok * 32 + half * 16 + j] = l;
    }
}

// ---------------------------------------------------------------------------
// K3: out = attn @ W_out + b_out. 256 thr, tile 128x128, ldmatrix loads.
// ---------------------------------------------------------------------------
__global__ __launch_bounds__(256) void out_mma_kernel(
    const float* __restrict__ bias, float* __restrict__ out)
{
    extern __shared__ __align__(16) unsigned so[];
    unsigned* Ah = so;
    unsigned* Al = so + 4608;
    unsigned* Bh = so + 9216;
    unsigned* Bl = so + 13824;

    const unsigned sbase = (unsigned)__cvta_generic_to_shared(so);
    const int t = threadIdx.x, lane = t & 31, warp = t >> 5;
    const int g = lane >> 2, tg = lane & 3;
    const int rr = lane & 7, tl = lane >> 3;
    const int m0 = blockIdx.x * 128;
    const int n0 = blockIdx.y * 128;
    const int rb = (warp & 3) * 32;
    const int cbn = (warp >> 2) * 64;

    const unsigned aoff = ((rb + rr + (tl & 1) * 8) * AS + (tl >> 1) * 4) * 4;
    const unsigned boff = ((cbn + rr + ((tl >> 1) & 1) * 8) * AS + (tl & 1) * 4) * 4;

    for (int i = t; i < 1024; i += 256) {
        int r = i >> 3, j = (i & 7) * 4;
        *(float4*)(Ah + r * AS + j) = *(const float4*)(g_attn_hi + (size_t)(m0 + r) * 32 + j);
        *(float4*)(Al + r * AS + j) = *(const float4*)(g_attn_lo + (size_t)(m0 + r) * 32 + j);
        *(float4*)(Bh + r * AS + j) = *(const float4*)(g_woT_hi + (size_t)(n0 + r) * 32 + j);
        *(float4*)(Bl + r * AS + j) = *(const float4*)(g_woT_lo + (size_t)(n0 + r) * 32 + j);
    }
    __syncthreads();

    float c[2][8][4] = {};
    #pragma unroll
    for (int kt = 0; kt < 4; kt++) {
        const unsigned ko = kt * 32;
        unsigned ah[2][4], al[2][4];
        LDSM4(ah[0][0], ah[0][1], ah[0][2], ah[0][3], sbase + aoff + ko);
        LDSM4(ah[1][0], ah[1][1], ah[1][2], ah[1][3], sbase + aoff + 16 * AS * 4 + ko);
        LDSM4(al[0][0], al[0][1], al[0][2], al[0][3], sbase + 4608 * 4 + aoff + ko);
        LDSM4(al[1][0], al[1][1], al[1][2], al[1][3], sbase + 4608 * 4 + aoff + 16 * AS * 4 + ko);
        #pragma unroll
        for (int ntp = 0; ntp < 4; ntp++) {
            unsigned bh0, bh1, bh2, bh3, bl0, bl1, bl2, bl3;
            LDSM4(bh0, bh1, bh2, bh3, sbase + 9216 * 4 + boff + ntp * 16 * AS * 4 + ko);
            LDSM4(bl0, bl1, bl2, bl3, sbase + 13824 * 4 + boff + ntp * 16 * AS * 4 + ko);
            #pragma unroll
            for (int gm = 0; gm < 2; gm++) {
                MMA16816(c[gm][2 * ntp],     ah[gm][0], ah[gm][1], ah[gm][2], ah[gm][3], bh0, bh1);
                MMA16816(c[gm][2 * ntp],     ah[gm][0], ah[gm][1], ah[gm][2], ah[gm][3], bl0, bl1);
                MMA16816(c[gm][2 * ntp],     al[gm][0], al[gm][1], al[gm][2], al[gm][3], bh0, bh1);
                MMA16816(c[gm][2 * ntp + 1], ah[gm][0], ah[gm][1], ah[gm][2], ah[gm][3], bh2, bh3);
                MMA16816(c[gm][2 * ntp + 1], ah[gm][0], ah[gm][1], ah[gm][2], ah[gm][3], bl2, bl3);
                MMA16816(c[gm][2 * ntp + 1], al[gm][0], al[gm][1], al[gm][2], al[gm][3], bh2, bh3);
            }
        }
    }

    #pragma unroll
    for (int gm = 0; gm < 2; gm++) {
        int row = m0 + rb + 16 * gm + g;
        #pragma unroll
        for (int nt = 0; nt < 8; nt++) {
            int col = n0 + cbn + 8 * nt + 2 * tg;
            float b0 = bias[col], b1 = bias[col + 1];
            *(float2*)(out + (size_t)row * DOUT + col)       = make_float2(c[gm][nt][0] + b0, c[gm][nt][1] + b1);
            *(float2*)(out + (size_t)(row + 8) * DOUT + col) = make_float2(c[gm][nt][2] + b0, c[gm][nt][3] + b1);
        }
    }
}

// ---------------------------------------------------------------------------
extern "C" void kernel_launch(void* const* d_in, const int* in_sizes, int n_in,
                              void* d_out, int out_size)
{
    const float* x    = (const float*)d_in[0];
    const float* Wqkv = (const float*)d_in[1];
    const float* Wout = (const float*)d_in[2];
    const float* bout = (const float*)d_in[3];
    float* out = (float*)d_out;

    prep_x_kernel<<<2048, 256>>>(x);
    prep_wqkv_kernel<<<192, 256>>>(Wqkv);
    prep_wout_kernel<<<64, 256>>>(Wout);

    cudaFuncSetAttribute(qkv_mma_kernel, cudaFuncAttributeMaxDynamicSharedMemorySize, 102400);
    qkv_mma_kernel<<<TOK / 128, 512, 102400>>>();

    cudaFuncSetAttribute(attn_mma_kernel, cudaFuncAttributeMaxDynamicSharedMemorySize, 110592);
    attn_mma_kernel<<<dim3(NCHUNK, NB), 256, 110592>>>();

    merge_kernel<<<dim3(28, NB), 256>>>();

    cudaFuncSetAttribute(out_mma_kernel, cudaFuncAttributeMaxDynamicSharedMemorySize, 73728);
    out_mma_kernel<<<dim3(TOK / 128, DOUT / 128), 256, 73728>>>(bout, out);
}

// round 11
// speedup vs baseline: 1.0508x; 1.0130x over previous
#include <cuda_runtime.h>
#include <cuda_bf16.h>

#define SEQ   4096
#define NB    4
#define TOK   (NB * SEQ)
#define DIN   512
#define DH    64
#define DOUT  512
#define NCHUNK 144                      // split-j chunks per batch (Br=128)
#define SCALE_LOG2E 0.1803368801111f    // 0.125 * log2(e)

// ---------------------------------------------------------------------------
// Device scratch (allocation-free). bf16 pairs packed in u32 words along k.
// ---------------------------------------------------------------------------
__device__ unsigned g_x_hi[TOK * (DIN/2)];
__device__ unsigned g_x_lo[TOK * (DIN/2)];
__device__ unsigned g_wqkvT_hi[192 * (DIN/2)];
__device__ unsigned g_wqkvT_lo[192 * (DIN/2)];
__device__ unsigned g_woT_hi[DOUT * (DH/2)];
__device__ unsigned g_woT_lo[DOUT * (DH/2)];
__device__ unsigned g_q_hi[TOK * (DH/2)];
__device__ unsigned g_q_lo[TOK * (DH/2)];
__device__ unsigned g_k_hi[TOK * (DH/2)];
__device__ unsigned g_k_lo[TOK * (DH/2)];
__device__ unsigned g_v_hi[TOK * (DH/2)];           // row-major like K
__device__ unsigned g_v_lo[TOK * (DH/2)];
__device__ unsigned g_attn_hi[TOK * (DH/2)];
__device__ unsigned g_attn_lo[TOK * (DH/2)];
__device__ float g_part_o[NB * NCHUNK * 128 * 64];  // unnormalized partial O
__device__ float g_part_m[NB * NCHUNK * 128];       // log2-domain row max
__device__ float g_part_l[NB * NCHUNK * 128];       // row sum

// ---------------------------------------------------------------------------
__device__ __forceinline__ void split2(float x0, float x1, unsigned &h, unsigned &l) {
    __nv_bfloat162 hh = __floats2bfloat162_rn(x0, x1);
    h = *reinterpret_cast<unsigned*>(&hh);
    float r0 = x0 - __bfloat162float(hh.x);
    float r1 = x1 - __bfloat162float(hh.y);
    __nv_bfloat162 ll = __floats2bfloat162_rn(r0, r1);
    l = *reinterpret_cast<unsigned*>(&ll);
}

#define MMA16816(c, a0, a1, a2, a3, b0, b1)                                   \
    asm volatile(                                                             \
        "mma.sync.aligned.m16n8k16.row.col.f32.bf16.bf16.f32 "                \
        "{%0,%1,%2,%3}, {%4,%5,%6,%7}, {%8,%9}, {%0,%1,%2,%3};\n"             \
        : "+f"((c)[0]), "+f"((c)[1]), "+f"((c)[2]), "+f"((c)[3])              \
        : "r"(a0), "r"(a1), "r"(a2), "r"(a3), "r"(b0), "r"(b1))

#define LDSM4(d0, d1, d2, d3, a)                                              \
    asm volatile("ldmatrix.sync.aligned.m8n8.x4.shared.b16 {%0,%1,%2,%3}, [%4];" \
        : "=r"(d0), "=r"(d1), "=r"(d2), "=r"(d3) : "r"(a))

#define LDSM4T(d0, d1, d2, d3, a)                                             \
    asm volatile("ldmatrix.sync.aligned.m8n8.x4.trans.shared.b16 {%0,%1,%2,%3}, [%4];" \
        : "=r"(d0), "=r"(d1), "=r"(d2), "=r"(d3) : "r"(a))

__device__ __forceinline__ void cpa16(unsigned dst, const void* src) {
    asm volatile("cp.async.cg.shared.global [%0], [%1], 16;\n" :: "r"(dst), "l"(src));
}
#define CP_COMMIT asm volatile("cp.async.commit_group;\n" ::: "memory")
#define CP_WAIT0  asm volatile("cp.async.wait_group 0;\n" ::: "memory")
#define CP_WAIT1  asm volatile("cp.async.wait_group 1;\n" ::: "memory")

// ---------------------------------------------------------------------------
// Prep kernels
// ---------------------------------------------------------------------------
__global__ __launch_bounds__(256) void prep_x_kernel(const float* __restrict__ x) {
    int i0 = blockIdx.x * 1024 + threadIdx.x;
    #pragma unroll
    for (int it = 0; it < 4; it++) {
        int idx = i0 + it * 256;
        float4 v = *(const float4*)(x + (size_t)idx * 4);
        unsigned h0, l0, h1, l1;
        split2(v.x, v.y, h0, l0);
        split2(v.z, v.w, h1, l1);
        g_x_hi[2 * idx] = h0; g_x_hi[2 * idx + 1] = h1;
        g_x_lo[2 * idx] = l0; g_x_lo[2 * idx + 1] = l1;
    }
}
__global__ __launch_bounds__(256) void prep_wqkv_kernel(const float* __restrict__ w) {
    int n = blockIdx.x, kw = threadIdx.x;
    float a = w[(size_t)(2 * kw) * 192 + n];
    float b = w[(size_t)(2 * kw + 1) * 192 + n];
    unsigned h, l; split2(a, b, h, l);
    g_wqkvT_hi[n * 256 + kw] = h; g_wqkvT_lo[n * 256 + kw] = l;
}
__global__ __launch_bounds__(256) void prep_wout_kernel(const float* __restrict__ w) {
    int idx = blockIdx.x * 256 + threadIdx.x;
    int n = idx >> 5, kw = idx & 31;
    float a = w[(size_t)(2 * kw) * DOUT + n];
    float b = w[(size_t)(2 * kw + 1) * DOUT + n];
    unsigned h, l; split2(a, b, h, l);
    g_woT_hi[n * 32 + kw] = h; g_woT_lo[n * 32 + kw] = l;
}

// ---------------------------------------------------------------------------
// K1: qkv GEMM, single-wave fat tile. 512 thr (16 warps: 4m x 4n), CTA tile
// M=128 x N=192, k-chunks 32, cp.async THREE-stage pipeline, ldmatrix.
// grid = 128 CTAs = one wave. Stage (12800 words): XH 0, XL 2560, WH 5120, WL 8960.
// ---------------------------------------------------------------------------
#define QS 20

__global__ __launch_bounds__(512) void qkv_mma_kernel() {
    extern __shared__ __align__(16) unsigned sq[];
    const unsigned sbase = (unsigned)__cvta_generic_to_shared(sq);
    const int t = threadIdx.x, lane = t & 31, warp = t >> 5;
    const int g = lane >> 2, tg = lane & 3;
    const int rr = lane & 7, tl = lane >> 3;
    const int m0 = blockIdx.x * 128;
    const int rb = (warp & 3) * 32;    // m-warp: 32 rows
    const int cb = (warp >> 2) * 48;   // n-warp: 48 cols

    const unsigned aoff = ((rb + rr + (tl & 1) * 8) * QS + (tl >> 1) * 4) * 4;
    const unsigned boff = ((cb + rr + ((tl >> 1) & 1) * 8) * QS + (tl & 1) * 4) * 4;

    auto prefetch = [&](int kc, int st) {
        unsigned sb = sbase + st * 12800 * 4;
        {   // X hi/lo: 512 float4 each, 1 per thread
            int r = t >> 2, j = (t & 3) * 4;
            cpa16(sb + (r * QS + j) * 4,          g_x_hi + (size_t)(m0 + r) * 256 + kc * 16 + j);
            cpa16(sb + (2560 + r * QS + j) * 4,   g_x_lo + (size_t)(m0 + r) * 256 + kc * 16 + j);
        }
        #pragma unroll
        for (int i = 0; i < 2; i++) {
            int idx = t + i * 512;
            if (idx < 768) {
                int r = idx >> 2, j = (idx & 3) * 4;
                cpa16(sb + (5120 + r * QS + j) * 4,   g_wqkvT_hi + (size_t)r * 256 + kc * 16 + j);
                cpa16(sb + (8960 + r * QS + j) * 4,   g_wqkvT_lo + (size_t)r * 256 + kc * 16 + j);
            }
        }
        CP_COMMIT;
    };

    float c[2][6][4] = {};
    prefetch(0, 0);
    prefetch(1, 1);

    for (int kc = 0; kc < 16; kc++) {
        const int st = kc % 3;
        if (kc + 2 < 16) { CP_WAIT1; } else { CP_WAIT0; }
        __syncthreads();
        if (kc + 2 < 16) prefetch(kc + 2, (kc + 2) % 3);

        const unsigned Xb = sbase + st * 12800 * 4;

        #pragma unroll
        for (int kt = 0; kt < 2; kt++) {
            const unsigned ko = kt * 32;   // 8 words
            unsigned ah[2][4], al[2][4];
            LDSM4(ah[0][0], ah[0][1], ah[0][2], ah[0][3], Xb + aoff + ko);
            LDSM4(ah[1][0], ah[1][1], ah[1][2], ah[1][3], Xb + aoff + 16 * QS * 4 + ko);
            LDSM4(al[0][0], al[0][1], al[0][2], al[0][3], Xb + 2560 * 4 + aoff + ko);
            LDSM4(al[1][0], al[1][1], al[1][2], al[1][3], Xb + 2560 * 4 + aoff + 16 * QS * 4 + ko);
            #pragma unroll
            for (int ntp = 0; ntp < 3; ntp++) {
                unsigned bh0, bh1, bh2, bh3, bl0, bl1, bl2, bl3;
                LDSM4(bh0, bh1, bh2, bh3, Xb + 5120 * 4 + boff + ntp * 16 * QS * 4 + ko);
                LDSM4(bl0, bl1, bl2, bl3, Xb + 8960 * 4 + boff + ntp * 16 * QS * 4 + ko);
                #pragma unroll
                for (int gm = 0; gm < 2; gm++) {
                    MMA16816(c[gm][2 * ntp],     ah[gm][0], ah[gm][1], ah[gm][2], ah[gm][3], bh0, bh1);
                    MMA16816(c[gm][2 * ntp],     ah[gm][0], ah[gm][1], ah[gm][2], ah[gm][3], bl0, bl1);
                    MMA16816(c[gm][2 * ntp],     al[gm][0], al[gm][1], al[gm][2], al[gm][3], bh0, bh1);
                    MMA16816(c[gm][2 * ntp + 1], ah[gm][0], ah[gm][1], ah[gm][2], ah[gm][3], bh2, bh3);
                    MMA16816(c[gm][2 * ntp + 1], ah[gm][0], ah[gm][1], ah[gm][2], ah[gm][3], bl2, bl3);
                    MMA16816(c[gm][2 * ntp + 1], al[gm][0], al[gm][1], al[gm][2], al[gm][3], bh2, bh3);
                }
            }
        }
    }

    // Epilogue: every n8 tile lies wholly in Q ([0,64)), K ([64,128)) or V ([128,192)).
    // All three now use identical coalesced row-major split stores.
    #pragma unroll
    for (int gm = 0; gm < 2; gm++) {
        int row = m0 + rb + 16 * gm + g;
        #pragma unroll
        for (int nt = 0; nt < 6; nt++) {
            int gcol = cb + 8 * nt;
            unsigned *oh, *ol;
            float qs2;
            int wd;
            if (gcol < 64)       { oh = g_q_hi; ol = g_q_lo; qs2 = SCALE_LOG2E; wd = (gcol >> 1) + tg; }
            else if (gcol < 128) { oh = g_k_hi; ol = g_k_lo; qs2 = 1.0f; wd = ((gcol - 64) >> 1) + tg; }
            else                 { oh = g_v_hi; ol = g_v_lo; qs2 = 1.0f; wd = ((gcol - 128) >> 1) + tg; }
            unsigned h, l;
            split2(c[gm][nt][0] * qs2, c[gm][nt][1] * qs2, h, l);
            oh[(size_t)row * 32 + wd] = h; ol[(size_t)row * 32 + wd] = l;
            split2(c[gm][nt][2] * qs2, c[gm][nt][3] * qs2, h, l);
            oh[(size_t)(row + 8) * 32 + wd] = h; ol[(size_t)(row + 8) * 32 + wd] = l;
        }
    }
}

// ---------------------------------------------------------------------------
// K2: split-j causal flash attention. 256 thr (8 warps), Br=128, Bc=64,
// cp.async 2-stage, ldmatrix fragment loads; V via ldmatrix.trans (row-major).
// ---------------------------------------------------------------------------
#define AS 36

__global__ __launch_bounds__(256) void attn_mma_kernel() {
    extern __shared__ __align__(16) unsigned sa[];
    const unsigned sbase = (unsigned)__cvta_generic_to_shared(sa);
    const int t = threadIdx.x, lane = t & 31, warp = t >> 5;
    const int g = lane >> 2, tg = lane & 3;
    const int rr = lane & 7, tl = lane >> 3;
    const int b = blockIdx.y;
    const int cx = blockIdx.x;

    int gr = 0;
    while (cx >= 2 * (gr + 1) * (gr + 2)) gr++;
    const int u = cx - 2 * gr * (gr + 1);
    const int ib = 4 * gr + u / (gr + 1);
    const int ci = u % (gr + 1);
    const int nch = gr + 1;
    const int jbeg = ci * 8;
    const int jend = min(jbeg + 8, 2 * ib + 2);
    const int i0 = ib * 128;

    // ldmatrix per-lane byte offsets
    const unsigned aoffQ = ((16 * warp + rr + (tl & 1) * 8) * AS + (tl >> 1) * 4) * 4;
    const unsigned boffB = ((rr + ((tl >> 1) & 1) * 8) * AS + (tl & 1) * 4) * 4;
    // trans-ldmatrix offset for V (row-major [token][d]):
    // matrix tl: token offset (tl&1)*8, d-col offset (tl>>1)*8 (=4 words)
    const unsigned voffT = ((rr + (tl & 1) * 8) * AS + (tl >> 1) * 4) * 4;

    // Q tile (plain loads; first loop sync covers visibility): 128 rows
    unsigned* Qh = sa;
    unsigned* Ql = sa + 4608;
    for (int i = t; i < 1024; i += 256) {
        int r = i >> 3, j = (i & 7) * 4;
        *(float4*)(Qh + r * AS + j) = *(const float4*)(g_q_hi + (size_t)(b * SEQ + i0 + r) * 32 + j);
        *(float4*)(Ql + r * AS + j) = *(const float4*)(g_q_lo + (size_t)(b * SEQ + i0 + r) * 32 + j);
    }

    auto prefetch = [&](int jt, int st) {
        unsigned sb = sbase + (9216 + st * 9216) * 4;
        #pragma unroll
        for (int i = 0; i < 2; i++) {
            int idx = t + i * 256;
            int r = idx >> 3, j = idx & 7;
            cpa16(sb + (r * AS + 4 * j) * 4,          g_k_hi + (size_t)(b * SEQ + jt * 64 + r) * 32 + 4 * j);
            cpa16(sb + (2304 + r * AS + 4 * j) * 4,   g_k_lo + (size_t)(b * SEQ + jt * 64 + r) * 32 + 4 * j);
            cpa16(sb + (4608 + r * AS + 4 * j) * 4,   g_v_hi + (size_t)(b * SEQ + jt * 64 + r) * 32 + 4 * j);
            cpa16(sb + (6912 + r * AS + 4 * j) * 4,   g_v_lo + (size_t)(b * SEQ + jt * 64 + r) * 32 + 4 * j);
        }
        CP_COMMIT;
    };

    float o[8][4] = {};
    float mrow[2] = {-1e30f, -1e30f};
    float lrow[2] = {0.f, 0.f};

    prefetch(jbeg, 0);

    for (int jt = jbeg; jt < jend; jt++) {
        const int st = (jt - jbeg) & 1;
        CP_WAIT0;
        __syncthreads();
        if (jt + 1 < jend) prefetch(jt + 1, st ^ 1);

        const unsigned KVb = sbase + (9216 + st * 9216) * 4;

        float c[8][4] = {};
        #pragma unroll
        for (int kt = 0; kt < 4; kt++) {
            const unsigned ko = kt * 32;
            unsigned ah0, ah1, ah2, ah3, al0, al1, al2, al3;
            LDSM4(ah0, ah1, ah2, ah3, sbase + aoffQ + ko);
            LDSM4(al0, al1, al2, al3, sbase + 4608 * 4 + aoffQ + ko);
            #pragma unroll
            for (int ntp = 0; ntp < 4; ntp++) {
                unsigned bh0, bh1, bh2, bh3, bl0, bl1, bl2, bl3;
                LDSM4(bh0, bh1, bh2, bh3, KVb + boffB + ntp * 16 * AS * 4 + ko);
                LDSM4(bl0, bl1, bl2, bl3, KVb + 2304 * 4 + boffB + ntp * 16 * AS * 4 + ko);
                MMA16816(c[2 * ntp],     ah0, ah1, ah2, ah3, bh0, bh1);
                MMA16816(c[2 * ntp],     ah0, ah1, ah2, ah3, bl0, bl1);
                MMA16816(c[2 * ntp],     al0, al1, al2, al3, bh0, bh1);
                MMA16816(c[2 * ntp + 1], ah0, ah1, ah2, ah3, bh2, bh3);
                MMA16816(c[2 * ntp + 1], ah0, ah1, ah2, ah3, bl2, bl3);
                MMA16816(c[2 * ntp + 1], al0, al1, al2, al3, bh2, bh3);
            }
        }

        if (jt >= 2 * ib) {   // partially-masked tiles (last two of the row-block)
            #pragma unroll
            for (int nt = 0; nt < 8; nt++) {
                #pragma unroll
                for (int e = 0; e < 4; e++) {
                    int row = i0 + 16 * warp + g + (e >= 2 ? 8 : 0);
                    int col = jt * 64 + 8 * nt + 2 * tg + (e & 1);
                    if (col > row) c[nt][e] = -1e30f;
                }
            }
        }

        float mx0 = -1e30f, mx1 = -1e30f;
        #pragma unroll
        for (int nt = 0; nt < 8; nt++) {
            mx0 = fmaxf(mx0, fmaxf(c[nt][0], c[nt][1]));
            mx1 = fmaxf(mx1, fmaxf(c[nt][2], c[nt][3]));
        }
        mx0 = fmaxf(mx0, __shfl_xor_sync(0xffffffffu, mx0, 1));
        mx0 = fmaxf(mx0, __shfl_xor_sync(0xffffffffu, mx0, 2));
        mx1 = fmaxf(mx1, __shfl_xor_sync(0xffffffffu, mx1, 1));
        mx1 = fmaxf(mx1, __shfl_xor_sync(0xffffffffu, mx1, 2));
        float mn0 = fmaxf(mrow[0], mx0), mn1 = fmaxf(mrow[1], mx1);
        float a0 = exp2f(mrow[0] - mn0), a1 = exp2f(mrow[1] - mn1);
        mrow[0] = mn0; mrow[1] = mn1;

        float s0 = 0.f, s1 = 0.f;
        #pragma unroll
        for (int nt = 0; nt < 8; nt++) {
            c[nt][0] = exp2f(c[nt][0] - mn0); s0 += c[nt][0];
            c[nt][1] = exp2f(c[nt][1] - mn0); s0 += c[nt][1];
            c[nt][2] = exp2f(c[nt][2] - mn1); s1 += c[nt][2];
            c[nt][3] = exp2f(c[nt][3] - mn1); s1 += c[nt][3];
        }
        s0 += __shfl_xor_sync(0xffffffffu, s0, 1);
        s0 += __shfl_xor_sync(0xffffffffu, s0, 2);
        s1 += __shfl_xor_sync(0xffffffffu, s1, 1);
        s1 += __shfl_xor_sync(0xffffffffu, s1, 2);
        lrow[0] = lrow[0] * a0 + s0;
        lrow[1] = lrow[1] * a1 + s1;
        #pragma unroll
        for (int nt = 0; nt < 8; nt++) {
            o[nt][0] *= a0; o[nt][1] *= a0; o[nt][2] *= a1; o[nt][3] *= a1;
        }

        #pragma unroll
        for (int kt = 0; kt < 4; kt++) {
            unsigned ah0, al0, ah1, al1, ah2, al2, ah3, al3;
            split2(c[2 * kt][0],     c[2 * kt][1],     ah0, al0);
            split2(c[2 * kt][2],     c[2 * kt][3],     ah1, al1);
            split2(c[2 * kt + 1][0], c[2 * kt + 1][1], ah2, al2);
            split2(c[2 * kt + 1][2], c[2 * kt + 1][3], ah3, al3);
            const unsigned kvo = kt * 16 * AS * 4;   // 16 token-rows per k-step
            #pragma unroll
            for (int ntp = 0; ntp < 4; ntp++) {
                unsigned bh0, bh1, bh2, bh3, bl0, bl1, bl2, bl3;
                LDSM4T(bh0, bh1, bh2, bh3, KVb + 4608 * 4 + voffT + kvo + ntp * 32);
                LDSM4T(bl0, bl1, bl2, bl3, KVb + 6912 * 4 + voffT + kvo + ntp * 32);
                MMA16816(o[2 * ntp],     ah0, ah1, ah2, ah3, bh0, bh1);
                MMA16816(o[2 * ntp],     ah0, ah1, ah2, ah3, bl0, bl1);
                MMA16816(o[2 * ntp],     al0, al1, al2, al3, bh0, bh1);
                MMA16816(o[2 * ntp + 1], ah0, ah1, ah2, ah3, bh2, bh3);
                MMA16816(o[2 * ntp + 1], ah0, ah1, ah2, ah3, bl2, bl3);
                MMA16816(o[2 * ntp + 1], al0, al1, al2, al3, bh2, bh3);
            }
        }
    }

    if (nch == 1) {
        float inv0 = 1.0f / lrow[0], inv1 = 1.0f / lrow[1];
        const int tok = b * SEQ + i0 + 16 * warp + g;
        #pragma unroll
        for (int nt = 0; nt < 8; nt++) {
            unsigned h, l;
            split2(o[nt][0] * inv0, o[nt][1] * inv0, h, l);
            g_attn_hi[(size_t)tok * 32 + 4 * nt + tg] = h;
            g_attn_lo[(size_t)tok * 32 + 4 * nt + tg] = l;
            split2(o[nt][2] * inv1, o[nt][3] * inv1, h, l);
            g_attn_hi[(size_t)(tok + 8) * 32 + 4 * nt + tg] = h;
            g_attn_lo[(size_t)(tok + 8) * 32 + 4 * nt + tg] = l;
        }
    } else {
        const int pb = b * NCHUNK + cx;
        const int r0 = 16 * warp + g;
        #pragma unroll
        for (int nt = 0; nt < 8; nt++) {
            int col = 8 * nt + 2 * tg;
            *(float2*)&g_part_o[((size_t)pb * 128 + r0) * 64 + col]     = make_float2(o[nt][0], o[nt][1]);
            *(float2*)&g_part_o[((size_t)pb * 128 + r0 + 8) * 64 + col] = make_float2(o[nt][2], o[nt][3]);
        }
        if (tg == 0) {
            g_part_m[pb * 128 + r0] = mrow[0];     g_part_l[pb * 128 + r0] = lrow[0];
            g_part_m[pb * 128 + r0 + 8] = mrow[1]; g_part_l[pb * 128 + r0 + 8] = lrow[1];
        }
    }
}

// ---------------------------------------------------------------------------
// K2b: merge split-j partials (row blocks ib >= 4; up to 8 chunks each)
// ---------------------------------------------------------------------------
__global__ __launch_bounds__(256) void merge_kernel() {
    const int ib = 4 + blockIdx.x;   // 4..31
    const int b = blockIdx.y;
    const int gr = ib >> 2;
    const int nch = gr + 1;
    const int cx0 = 2 * gr * (gr + 1) + (ib - 4 * gr) * (gr + 1);

    const int t = threadIdx.x;
    const int r = t >> 1, half = t & 1;   // r in 0..127

    float mc[8], lc[8], wv[8];
    float mstar = -1e30f;
    for (int c = 0; c < nch; c++) {
        mc[c] = g_part_m[(b * NCHUNK + cx0 + c) * 128 + r];
        lc[c] = g_part_l[(b * NCHUNK + cx0 + c) * 128 + r];
        mstar = fmaxf(mstar, mc[c]);
    }
    float lsum = 0.f;
    for (int c = 0; c < nch; c++) { wv[c] = exp2f(mc[c] - mstar); lsum += wv[c] * lc[c]; }
    const float inv = 1.0f / lsum;

    const int tok = b * SEQ + ib * 128 + r;
    #pragma unroll 4
    for (int j = 0; j < 16; j++) {
        int col = half * 32 + 2 * j;
        float a0 = 0.f, a1 = 0.f;
        for (int c = 0; c < nch; c++) {
            float2 v = *(const float2*)&g_part_o[((size_t)(b * NCHUNK + cx0 + c) * 128 + r) * 64 + col];
            a0 += wv[c] * v.x; a1 += wv[c] * v.y;
        }
        unsigned h, l; split2(a0 * inv, a1 * inv, h, l);
        g_attn_hi[(size_t)tok * 32 + half * 16 + j] = h;
        g_attn_lo[(size_t)tok * 32 + half * 16 + j] = l;
    }
}

// ---------------------------------------------------------------------------
// K3: out = attn @ W_out + b_out. 256 thr, tile 128x128, ldmatrix loads.
// ---------------------------------------------------------------------------
__global__ __launch_bounds__(256) void out_mma_kernel(
    const float* __restrict__ bias, float* __restrict__ out)
{
    extern __shared__ __align__(16) unsigned so[];
    unsigned* Ah = so;
    unsigned* Al = so + 4608;
    unsigned* Bh = so + 9216;
    unsigned* Bl = so + 13824;

    const unsigned sbase = (unsigned)__cvta_generic_to_shared(so);
    const int t = threadIdx.x, lane = t & 31, warp = t >> 5;
    const int g = lane >> 2, tg = lane & 3;
    const int rr = lane & 7, tl = lane >> 3;
    const int m0 = blockIdx.x * 128;
    const int n0 = blockIdx.y * 128;
    const int rb = (warp & 3) * 32;
    const int cbn = (warp >> 2) * 64;

    const unsigned aoff = ((rb + rr + (tl & 1) * 8) * AS + (tl >> 1) * 4) * 4;
    const unsigned boff = ((cbn + rr + ((tl >> 1) & 1) * 8) * AS + (tl & 1) * 4) * 4;

    for (int i = t; i < 1024; i += 256) {
        int r = i >> 3, j = (i & 7) * 4;
        *(float4*)(Ah + r * AS + j) = *(const float4*)(g_attn_hi + (size_t)(m0 + r) * 32 + j);
        *(float4*)(Al + r * AS + j) = *(const float4*)(g_attn_lo + (size_t)(m0 + r) * 32 + j);
        *(float4*)(Bh + r * AS + j) = *(const float4*)(g_woT_hi + (size_t)(n0 + r) * 32 + j);
        *(float4*)(Bl + r * AS + j) = *(const float4*)(g_woT_lo + (size_t)(n0 + r) * 32 + j);
    }
    __syncthreads();

    float c[2][8][4] = {};
    #pragma unroll
    for (int kt = 0; kt < 4; kt++) {
        const unsigned ko = kt * 32;
        unsigned ah[2][4], al[2][4];
        LDSM4(ah[0][0], ah[0][1], ah[0][2], ah[0][3], sbase + aoff + ko);
        LDSM4(ah[1][0], ah[1][1], ah[1][2], ah[1][3], sbase + aoff + 16 * AS * 4 + ko);
        LDSM4(al[0][0], al[0][1], al[0][2], al[0][3], sbase + 4608 * 4 + aoff + ko);
        LDSM4(al[1][0], al[1][1], al[1][2], al[1][3], sbase + 4608 * 4 + aoff + 16 * AS * 4 + ko);
        #pragma unroll
        for (int ntp = 0; ntp < 4; ntp++) {
            unsigned bh0, bh1, bh2, bh3, bl0, bl1, bl2, bl3;
            LDSM4(bh0, bh1, bh2, bh3, sbase + 9216 * 4 + boff + ntp * 16 * AS * 4 + ko);
            LDSM4(bl0, bl1, bl2, bl3, sbase + 13824 * 4 + boff + ntp * 16 * AS * 4 + ko);
            #pragma unroll
            for (int gm = 0; gm < 2; gm++) {
                MMA16816(c[gm][2 * ntp],     ah[gm][0], ah[gm][1], ah[gm][2], ah[gm][3], bh0, bh1);
                MMA16816(c[gm][2 * ntp],     ah[gm][0], ah[gm][1], ah[gm][2], ah[gm][3], bl0, bl1);
                MMA16816(c[gm][2 * ntp],     al[gm][0], al[gm][1], al[gm][2], al[gm][3], bh0, bh1);
                MMA16816(c[gm][2 * ntp + 1], ah[gm][0], ah[gm][1], ah[gm][2], ah[gm][3], bh2, bh3);
                MMA16816(c[gm][2 * ntp + 1], ah[gm][0], ah[gm][1], ah[gm][2], ah[gm][3], bl2, bl3);
                MMA16816(c[gm][2 * ntp + 1], al[gm][0], al[gm][1], al[gm][2], al[gm][3], bh2, bh3);
            }
        }
    }

    #pragma unroll
    for (int gm = 0; gm < 2; gm++) {
        int row = m0 + rb + 16 * gm + g;
        #pragma unroll
        for (int nt = 0; nt < 8; nt++) {
            int col = n0 + cbn + 8 * nt + 2 * tg;
            float b0 = bias[col], b1 = bias[col + 1];
            *(float2*)(out + (size_t)row * DOUT + col)       = make_float2(c[gm][nt][0] + b0, c[gm][nt][1] + b1);
            *(float2*)(out + (size_t)(row + 8) * DOUT + col) = make_float2(c[gm][nt][2] + b0, c[gm][nt][3] + b1);
        }
    }
}

// ---------------------------------------------------------------------------
extern "C" void kernel_launch(void* const* d_in, const int* in_sizes, int n_in,
                              void* d_out, int out_size)
{
    const float* x    = (const float*)d_in[0];
    const float* Wqkv = (const float*)d_in[1];
    const float* Wout = (const float*)d_in[2];
    const float* bout = (const float*)d_in[3];
    float* out = (float*)d_out;

    prep_x_kernel<<<2048, 256>>>(x);
    prep_wqkv_kernel<<<192, 256>>>(Wqkv);
    prep_wout_kernel<<<64, 256>>>(Wout);

    cudaFuncSetAttribute(qkv_mma_kernel, cudaFuncAttributeMaxDynamicSharedMemorySize, 153600);
    qkv_mma_kernel<<<TOK / 128, 512, 153600>>>();

    cudaFuncSetAttribute(attn_mma_kernel, cudaFuncAttributeMaxDynamicSharedMemorySize, 110592);
    attn_mma_kernel<<<dim3(NCHUNK, NB), 256, 110592>>>();

    merge_kernel<<<dim3(28, NB), 256>>>();

    cudaFuncSetAttribute(out_mma_kernel, cudaFuncAttributeMaxDynamicSharedMemorySize, 73728);
    out_mma_kernel<<<dim3(TOK / 128, DOUT / 128), 256, 73728>>>(bout, out);
}

// round 14
// speedup vs baseline: 1.0856x; 1.0331x over previous
#include <cuda_runtime.h>
#include <cuda_bf16.h>

#define SEQ   4096
#define NB    4
#define TOK   (NB * SEQ)
#define DIN   512
#define DH    64
#define DOUT  512
#define NCHUNK 144                      // split-j chunks per batch (Br=128)
#define SCALE_LOG2E 0.1803368801111f    // 0.125 * log2(e)

// ---------------------------------------------------------------------------
// Device scratch (allocation-free). bf16 pairs packed in u32 words along k.
// ---------------------------------------------------------------------------
__device__ unsigned g_x_hi[TOK * (DIN/2)];
__device__ unsigned g_x_lo[TOK * (DIN/2)];
__device__ unsigned g_wqkvT_hi[192 * (DIN/2)];
__device__ unsigned g_wqkvT_lo[192 * (DIN/2)];
__device__ unsigned g_woT_hi[DOUT * (DH/2)];
__device__ unsigned g_woT_lo[DOUT * (DH/2)];
__device__ unsigned g_q_hi[TOK * (DH/2)];
__device__ unsigned g_q_lo[TOK * (DH/2)];
__device__ unsigned g_k_hi[TOK * (DH/2)];
__device__ unsigned g_k_lo[TOK * (DH/2)];
__device__ unsigned g_v_hi[TOK * (DH/2)];           // row-major like K
__device__ unsigned g_v_lo[TOK * (DH/2)];
__device__ unsigned g_attn_hi[TOK * (DH/2)];
__device__ unsigned g_attn_lo[TOK * (DH/2)];
__device__ float g_part_o[NB * NCHUNK * 128 * 64];  // unnormalized partial O
__device__ float g_part_m[NB * NCHUNK * 128];       // log2-domain row max
__device__ float g_part_l[NB * NCHUNK * 128];       // row sum

// ---------------------------------------------------------------------------
__device__ __forceinline__ void split2(float x0, float x1, unsigned &h, unsigned &l) {
    __nv_bfloat162 hh = __floats2bfloat162_rn(x0, x1);
    h = *reinterpret_cast<unsigned*>(&hh);
    float r0 = x0 - __bfloat162float(hh.x);
    float r1 = x1 - __bfloat162float(hh.y);
    __nv_bfloat162 ll = __floats2bfloat162_rn(r0, r1);
    l = *reinterpret_cast<unsigned*>(&ll);
}

#define MMA16816(c, a0, a1, a2, a3, b0, b1)                                   \
    asm volatile(                                                             \
        "mma.sync.aligned.m16n8k16.row.col.f32.bf16.bf16.f32 "                \
        "{%0,%1,%2,%3}, {%4,%5,%6,%7}, {%8,%9}, {%0,%1,%2,%3};\n"             \
        : "+f"((c)[0]), "+f"((c)[1]), "+f"((c)[2]), "+f"((c)[3])              \
        : "r"(a0), "r"(a1), "r"(a2), "r"(a3), "r"(b0), "r"(b1))

#define LDSM4(d0, d1, d2, d3, a)                                              \
    asm volatile("ldmatrix.sync.aligned.m8n8.x4.shared.b16 {%0,%1,%2,%3}, [%4];" \
        : "=r"(d0), "=r"(d1), "=r"(d2), "=r"(d3) : "r"(a))

#define LDSM4T(d0, d1, d2, d3, a)                                             \
    asm volatile("ldmatrix.sync.aligned.m8n8.x4.trans.shared.b16 {%0,%1,%2,%3}, [%4];" \
        : "=r"(d0), "=r"(d1), "=r"(d2), "=r"(d3) : "r"(a))

__device__ __forceinline__ void cpa16(unsigned dst, const void* src) {
    asm volatile("cp.async.cg.shared.global [%0], [%1], 16;\n" :: "r"(dst), "l"(src));
}
#define CP_COMMIT asm volatile("cp.async.commit_group;\n" ::: "memory")
#define CP_WAIT0  asm volatile("cp.async.wait_group 0;\n" ::: "memory")

// ---------------------------------------------------------------------------
// Fused prep kernel: blocks [0,2048) split x; [2048,2240) W_qkv^T; [2240,2304) W_out^T.
// ---------------------------------------------------------------------------
__global__ __launch_bounds__(256) void prep_all_kernel(
    const float* __restrict__ x, const float* __restrict__ wqkv,
    const float* __restrict__ wout)
{
    const int bx = blockIdx.x;
    if (bx < 2048) {
        int i0 = bx * 1024 + threadIdx.x;
        #pragma unroll
        for (int it = 0; it < 4; it++) {
            int idx = i0 + it * 256;
            float4 v = *(const float4*)(x + (size_t)idx * 4);
            unsigned h0, l0, h1, l1;
            split2(v.x, v.y, h0, l0);
            split2(v.z, v.w, h1, l1);
            g_x_hi[2 * idx] = h0; g_x_hi[2 * idx + 1] = h1;
            g_x_lo[2 * idx] = l0; g_x_lo[2 * idx + 1] = l1;
        }
    } else if (bx < 2240) {
        int n = bx - 2048, kw = threadIdx.x;
        float a = wqkv[(size_t)(2 * kw) * 192 + n];
        float b = wqkv[(size_t)(2 * kw + 1) * 192 + n];
        unsigned h, l; split2(a, b, h, l);
        g_wqkvT_hi[n * 256 + kw] = h; g_wqkvT_lo[n * 256 + kw] = l;
    } else {
        int idx = (bx - 2240) * 256 + threadIdx.x;
        int n = idx >> 5, kw = idx & 31;
        float a = wout[(size_t)(2 * kw) * DOUT + n];
        float b = wout[(size_t)(2 * kw + 1) * DOUT + n];
        unsigned h, l; split2(a, b, h, l);
        g_woT_hi[n * 32 + kw] = h; g_woT_lo[n * 32 + kw] = l;
    }
}

// ---------------------------------------------------------------------------
// K1: qkv GEMM, single-wave fat tile. 512 thr (16 warps: 4m x 4n), CTA tile
// M=128 x N=192, k-chunks 32, cp.async TWO-stage, ldmatrix. grid = 128 CTAs.
// Stage (12800 words): XH 0, XL 2560, WH 5120, WL 8960.
// ---------------------------------------------------------------------------
#define QS 20

__global__ __launch_bounds__(512) void qkv_mma_kernel() {
    extern __shared__ __align__(16) unsigned sq[];
    const unsigned sbase = (unsigned)__cvta_generic_to_shared(sq);
    const int t = threadIdx.x, lane = t & 31, warp = t >> 5;
    const int g = lane >> 2, tg = lane & 3;
    const int rr = lane & 7, tl = lane >> 3;
    const int m0 = blockIdx.x * 128;
    const int rb = (warp & 3) * 32;    // m-warp: 32 rows
    const int cb = (warp >> 2) * 48;   // n-warp: 48 cols

    const unsigned aoff = ((rb + rr + (tl & 1) * 8) * QS + (tl >> 1) * 4) * 4;
    const unsigned boff = ((cb + rr + ((tl >> 1) & 1) * 8) * QS + (tl & 1) * 4) * 4;

    auto prefetch = [&](int kc, int st) {
        unsigned sb = sbase + st * 12800 * 4;
        {   // X hi/lo: 512 float4 each, 1 per thread
            int r = t >> 2, j = (t & 3) * 4;
            cpa16(sb + (r * QS + j) * 4,          g_x_hi + (size_t)(m0 + r) * 256 + kc * 16 + j);
            cpa16(sb + (2560 + r * QS + j) * 4,   g_x_lo + (size_t)(m0 + r) * 256 + kc * 16 + j);
        }
        #pragma unroll
        for (int i = 0; i < 2; i++) {
            int idx = t + i * 512;
            if (idx < 768) {
                int r = idx >> 2, j = (idx & 3) * 4;
                cpa16(sb + (5120 + r * QS + j) * 4,   g_wqkvT_hi + (size_t)r * 256 + kc * 16 + j);
                cpa16(sb + (8960 + r * QS + j) * 4,   g_wqkvT_lo + (size_t)r * 256 + kc * 16 + j);
            }
        }
        CP_COMMIT;
    };

    float c[2][6][4] = {};
    prefetch(0, 0);

    for (int kc = 0; kc < 16; kc++) {
        const int st = kc & 1;
        CP_WAIT0;
        __syncthreads();
        if (kc + 1 < 16) prefetch(kc + 1, st ^ 1);

        const unsigned Xb = sbase + st * 12800 * 4;

        #pragma unroll
        for (int kt = 0; kt < 2; kt++) {
            const unsigned ko = kt * 32;   // 8 words
            unsigned ah[2][4], al[2][4];
            LDSM4(ah[0][0], ah[0][1], ah[0][2], ah[0][3], Xb + aoff + ko);
            LDSM4(ah[1][0], ah[1][1], ah[1][2], ah[1][3], Xb + aoff + 16 * QS * 4 + ko);
            LDSM4(al[0][0], al[0][1], al[0][2], al[0][3], Xb + 2560 * 4 + aoff + ko);
            LDSM4(al[1][0], al[1][1], al[1][2], al[1][3], Xb + 2560 * 4 + aoff + 16 * QS * 4 + ko);
            #pragma unroll
            for (int ntp = 0; ntp < 3; ntp++) {
                unsigned bh0, bh1, bh2, bh3, bl0, bl1, bl2, bl3;
                LDSM4(bh0, bh1, bh2, bh3, Xb + 5120 * 4 + boff + ntp * 16 * QS * 4 + ko);
                LDSM4(bl0, bl1, bl2, bl3, Xb + 8960 * 4 + boff + ntp * 16 * QS * 4 + ko);
                #pragma unroll
                for (int gm = 0; gm < 2; gm++) {
                    MMA16816(c[gm][2 * ntp],     ah[gm][0], ah[gm][1], ah[gm][2], ah[gm][3], bh0, bh1);
                    MMA16816(c[gm][2 * ntp],     ah[gm][0], ah[gm][1], ah[gm][2], ah[gm][3], bl0, bl1);
                    MMA16816(c[gm][2 * ntp],     al[gm][0], al[gm][1], al[gm][2], al[gm][3], bh0, bh1);
                    MMA16816(c[gm][2 * ntp + 1], ah[gm][0], ah[gm][1], ah[gm][2], ah[gm][3], bh2, bh3);
                    MMA16816(c[gm][2 * ntp + 1], ah[gm][0], ah[gm][1], ah[gm][2], ah[gm][3], bl2, bl3);
                    MMA16816(c[gm][2 * ntp + 1], al[gm][0], al[gm][1], al[gm][2], al[gm][3], bh2, bh3);
                }
            }
        }
    }

    // Epilogue: every n8 tile lies wholly in Q ([0,64)), K ([64,128)) or V ([128,192)).
    #pragma unroll
    for (int gm = 0; gm < 2; gm++) {
        int row = m0 + rb + 16 * gm + g;
        #pragma unroll
        for (int nt = 0; nt < 6; nt++) {
            int gcol = cb + 8 * nt;
            unsigned *oh, *ol;
            float qs2;
            int wd;
            if (gcol < 64)       { oh = g_q_hi; ol = g_q_lo; qs2 = SCALE_LOG2E; wd = (gcol >> 1) + tg; }
            else if (gcol < 128) { oh = g_k_hi; ol = g_k_lo; qs2 = 1.0f; wd = ((gcol - 64) >> 1) + tg; }
            else                 { oh = g_v_hi; ol = g_v_lo; qs2 = 1.0f; wd = ((gcol - 128) >> 1) + tg; }
            unsigned h, l;
            split2(c[gm][nt][0] * qs2, c[gm][nt][1] * qs2, h, l);
            oh[(size_t)row * 32 + wd] = h; ol[(size_t)row * 32 + wd] = l;
            split2(c[gm][nt][2] * qs2, c[gm][nt][3] * qs2, h, l);
            oh[(size_t)(row + 8) * 32 + wd] = h; ol[(size_t)(row + 8) * 32 + wd] = l;
        }
    }
}

// ---------------------------------------------------------------------------
// K2: split-j causal flash attention. 256 thr (8 warps), Br=128, Bc=64,
// cp.async 2-stage, ldmatrix fragment loads; V via ldmatrix.trans (row-major).
// ---------------------------------------------------------------------------
#define AS 36

__global__ __launch_bounds__(256) void attn_mma_kernel() {
    extern __shared__ __align__(16) unsigned sa[];
    const unsigned sbase = (unsigned)__cvta_generic_to_shared(sa);
    const int t = threadIdx.x, lane = t & 31, warp = t >> 5;
    const int g = lane >> 2, tg = lane & 3;
    const int rr = lane & 7, tl = lane >> 3;
    const int b = blockIdx.y;
    const int cx = blockIdx.x;

    int gr = 0;
    while (cx >= 2 * (gr + 1) * (gr + 2)) gr++;
    const int u = cx - 2 * gr * (gr + 1);
    const int ib = 4 * gr + u / (gr + 1);
    const int ci = u % (gr + 1);
    const int nch = gr + 1;
    const int jbeg = ci * 8;
    const int jend = min(jbeg + 8, 2 * ib + 2);
    const int i0 = ib * 128;

    const unsigned aoffQ = ((16 * warp + rr + (tl & 1) * 8) * AS + (tl >> 1) * 4) * 4;
    const unsigned boffB = ((rr + ((tl >> 1) & 1) * 8) * AS + (tl & 1) * 4) * 4;
    const unsigned voffT = ((rr + (tl & 1) * 8) * AS + (tl >> 1) * 4) * 4;

    unsigned* Qh = sa;
    unsigned* Ql = sa + 4608;
    for (int i = t; i < 1024; i += 256) {
        int r = i >> 3, j = (i & 7) * 4;
        *(float4*)(Qh + r * AS + j) = *(const float4*)(g_q_hi + (size_t)(b * SEQ + i0 + r) * 32 + j);
        *(float4*)(Ql + r * AS + j) = *(const float4*)(g_q_lo + (size_t)(b * SEQ + i0 + r) * 32 + j);
    }

    auto prefetch = [&](int jt, int st) {
        unsigned sb = sbase + (9216 + st * 9216) * 4;
        #pragma unroll
        for (int i = 0; i < 2; i++) {
            int idx = t + i * 256;
            int r = idx >> 3, j = idx & 7;
            cpa16(sb + (r * AS + 4 * j) * 4,          g_k_hi + (size_t)(b * SEQ + jt * 64 + r) * 32 + 4 * j);
            cpa16(sb + (2304 + r * AS + 4 * j) * 4,   g_k_lo + (size_t)(b * SEQ + jt * 64 + r) * 32 + 4 * j);
            cpa16(sb + (4608 + r * AS + 4 * j) * 4,   g_v_hi + (size_t)(b * SEQ + jt * 64 + r) * 32 + 4 * j);
            cpa16(sb + (6912 + r * AS + 4 * j) * 4,   g_v_lo + (size_t)(b * SEQ + jt * 64 + r) * 32 + 4 * j);
        }
        CP_COMMIT;
    };

    float o[8][4] = {};
    float mrow[2] = {-1e30f, -1e30f};
    float lrow[2] = {0.f, 0.f};

    prefetch(jbeg, 0);

    for (int jt = jbeg; jt < jend; jt++) {
        const int st = (jt - jbeg) & 1;
        CP_WAIT0;
        __syncthreads();
        if (jt + 1 < jend) prefetch(jt + 1, st ^ 1);

        const unsigned KVb = sbase + (9216 + st * 9216) * 4;

        float c[8][4] = {};
        #pragma unroll
        for (int kt = 0; kt < 4; kt++) {
            const unsigned ko = kt * 32;
            unsigned ah0, ah1, ah2, ah3, al0, al1, al2, al3;
            LDSM4(ah0, ah1, ah2, ah3, sbase + aoffQ + ko);
            LDSM4(al0, al1, al2, al3, sbase + 4608 * 4 + aoffQ + ko);
            #pragma unroll
            for (int ntp = 0; ntp < 4; ntp++) {
                unsigned bh0, bh1, bh2, bh3, bl0, bl1, bl2, bl3;
                LDSM4(bh0, bh1, bh2, bh3, KVb + boffB + ntp * 16 * AS * 4 + ko);
                LDSM4(bl0, bl1, bl2, bl3, KVb + 2304 * 4 + boffB + ntp * 16 * AS * 4 + ko);
                MMA16816(c[2 * ntp],     ah0, ah1, ah2, ah3, bh0, bh1);
                MMA16816(c[2 * ntp],     ah0, ah1, ah2, ah3, bl0, bl1);
                MMA16816(c[2 * ntp],     al0, al1, al2, al3, bh0, bh1);
                MMA16816(c[2 * ntp + 1], ah0, ah1, ah2, ah3, bh2, bh3);
                MMA16816(c[2 * ntp + 1], ah0, ah1, ah2, ah3, bl2, bl3);
                MMA16816(c[2 * ntp + 1], al0, al1, al2, al3, bh2, bh3);
            }
        }

        if (jt >= 2 * ib) {
            #pragma unroll
            for (int nt = 0; nt < 8; nt++) {
                #pragma unroll
                for (int e = 0; e < 4; e++) {
                    int row = i0 + 16 * warp + g + (e >= 2 ? 8 : 0);
                    int col = jt * 64 + 8 * nt + 2 * tg + (e & 1);
                    if (col > row) c[nt][e] = -1e30f;
                }
            }
        }

        float mx0 = -1e30f, mx1 = -1e30f;
        #pragma unroll
        for (int nt = 0; nt < 8; nt++) {
            mx0 = fmaxf(mx0, fmaxf(c[nt][0], c[nt][1]));
            mx1 = fmaxf(mx1, fmaxf(c[nt][2], c[nt][3]));
        }
        mx0 = fmaxf(mx0, __shfl_xor_sync(0xffffffffu, mx0, 1));
        mx0 = fmaxf(mx0, __shfl_xor_sync(0xffffffffu, mx0, 2));
        mx1 = fmaxf(mx1, __shfl_xor_sync(0xffffffffu, mx1, 1));
        mx1 = fmaxf(mx1, __shfl_xor_sync(0xffffffffu, mx1, 2));
        float mn0 = fmaxf(mrow[0], mx0), mn1 = fmaxf(mrow[1], mx1);
        float a0 = exp2f(mrow[0] - mn0), a1 = exp2f(mrow[1] - mn1);
        mrow[0] = mn0; mrow[1] = mn1;

        float s0 = 0.f, s1 = 0.f;
        #pragma unroll
        for (int nt = 0; nt < 8; nt++) {
            c[nt][0] = exp2f(c[nt][0] - mn0); s0 += c[nt][0];
            c[nt][1] = exp2f(c[nt][1] - mn0); s0 += c[nt][1];
            c[nt][2] = exp2f(c[nt][2] - mn1); s1 += c[nt][2];
            c[nt][3] = exp2f(c[nt][3] - mn1); s1 += c[nt][3];
        }
        s0 += __shfl_xor_sync(0xffffffffu, s0, 1);
        s0 += __shfl_xor_sync(0xffffffffu, s0, 2);
        s1 += __shfl_xor_sync(0xffffffffu, s1, 1);
        s1 += __shfl_xor_sync(0xffffffffu, s1, 2);
        lrow[0] = lrow[0] * a0 + s0;
        lrow[1] = lrow[1] * a1 + s1;
        #pragma unroll
        for (int nt = 0; nt < 8; nt++) {
            o[nt][0] *= a0; o[nt][1] *= a0; o[nt][2] *= a1; o[nt][3] *= a1;
        }

        #pragma unroll
        for (int kt = 0; kt < 4; kt++) {
            unsigned ah0, al0, ah1, al1, ah2, al2, ah3, al3;
            split2(c[2 * kt][0],     c[2 * kt][1],     ah0, al0);
            split2(c[2 * kt][2],     c[2 * kt][3],     ah1, al1);
            split2(c[2 * kt + 1][0], c[2 * kt + 1][1], ah2, al2);
            split2(c[2 * kt + 1][2], c[2 * kt + 1][3], ah3, al3);
            const unsigned kvo = kt * 16 * AS * 4;
            #pragma unroll
            for (int ntp = 0; ntp < 4; ntp++) {
                unsigned bh0, bh1, bh2, bh3, bl0, bl1, bl2, bl3;
                LDSM4T(bh0, bh1, bh2, bh3, KVb + 4608 * 4 + voffT + kvo + ntp * 32);
                LDSM4T(bl0, bl1, bl2, bl3, KVb + 6912 * 4 + voffT + kvo + ntp * 32);
                MMA16816(o[2 * ntp],     ah0, ah1, ah2, ah3, bh0, bh1);
                MMA16816(o[2 * ntp],     ah0, ah1, ah2, ah3, bl0, bl1);
                MMA16816(o[2 * ntp],     al0, al1, al2, al3, bh0, bh1);
                MMA16816(o[2 * ntp + 1], ah0, ah1, ah2, ah3, bh2, bh3);
                MMA16816(o[2 * ntp + 1], ah0, ah1, ah2, ah3, bl2, bl3);
                MMA16816(o[2 * ntp + 1], al0, al1, al2, al3, bh2, bh3);
            }
        }
    }

    if (nch == 1) {
        float inv0 = 1.0f / lrow[0], inv1 = 1.0f / lrow[1];
        const int tok = b * SEQ + i0 + 16 * warp + g;
        #pragma unroll
        for (int nt = 0; nt < 8; nt++) {
            unsigned h, l;
            split2(o[nt][0] * inv0, o[nt][1] * inv0, h, l);
            g_attn_hi[(size_t)tok * 32 + 4 * nt + tg] = h;
            g_attn_lo[(size_t)tok * 32 + 4 * nt + tg] = l;
            split2(o[nt][2] * inv1, o[nt][3] * inv1, h, l);
            g_attn_hi[(size_t)(tok + 8) * 32 + 4 * nt + tg] = h;
            g_attn_lo[(size_t)(tok + 8) * 32 + 4 * nt + tg] = l;
        }
    } else {
        const int pb = b * NCHUNK + cx;
        const int r0 = 16 * warp + g;
        #pragma unroll
        for (int nt = 0; nt < 8; nt++) {
            int col = 8 * nt + 2 * tg;
            *(float2*)&g_part_o[((size_t)pb * 128 + r0) * 64 + col]     = make_float2(o[nt][0], o[nt][1]);
            *(float2*)&g_part_o[((size_t)pb * 128 + r0 + 8) * 64 + col] = make_float2(o[nt][2], o[nt][3]);
        }
        if (tg == 0) {
            g_part_m[pb * 128 + r0] = mrow[0];     g_part_l[pb * 128 + r0] = lrow[0];
            g_part_m[pb * 128 + r0 + 8] = mrow[1]; g_part_l[pb * 128 + r0 + 8] = lrow[1];
        }
    }
}

// ---------------------------------------------------------------------------
// K2b: merge split-j partials (row blocks ib >= 4; up to 8 chunks each)
// ---------------------------------------------------------------------------
__global__ __launch_bounds__(256) void merge_kernel() {
    const int ib = 4 + blockIdx.x;   // 4..31
    const int b = blockIdx.y;
    const int gr = ib >> 2;
    const int nch = gr + 1;
    const int cx0 = 2 * gr * (gr + 1) + (ib - 4 * gr) * (gr + 1);

    const int t = threadIdx.x;
    const int r = t >> 1, half = t & 1;   // r in 0..127

    float mc[8], lc[8], wv[8];
    float mstar = -1e30f;
    for (int c = 0; c < nch; c++) {
        mc[c] = g_part_m[(b * NCHUNK + cx0 + c) * 128 + r];
        lc[c] = g_part_l[(b * NCHUNK + cx0 + c) * 128 + r];
        mstar = fmaxf(mstar, mc[c]);
    }
    float lsum = 0.f;
    for (int c = 0; c < nch; c++) { wv[c] = exp2f(mc[c] - mstar); lsum += wv[c] * lc[c]; }
    const float inv = 1.0f / lsum;

    const int tok = b * SEQ + ib * 128 + r;
    #pragma unroll 4
    for (int j = 0; j < 16; j++) {
        int col = half * 32 + 2 * j;
        float a0 = 0.f, a1 = 0.f;
        for (int c = 0; c < nch; c++) {
            float2 v = *(const float2*)&g_part_o[((size_t)(b * NCHUNK + cx0 + c) * 128 + r) * 64 + col];
            a0 += wv[c] * v.x; a1 += wv[c] * v.y;
        }
        unsigned h, l; split2(a0 * inv, a1 * inv, h, l);
        g_attn_hi[(size_t)tok * 32 + half * 16 + j] = h;
        g_attn_lo[(size_t)tok * 32 + half * 16 + j] = l;
    }
}

// ---------------------------------------------------------------------------
// K3: out = attn @ W_out + b_out. 256 thr, tile 128x128, ldmatrix loads.
// ---------------------------------------------------------------------------
__global__ __launch_bounds__(256) void out_mma_kernel(
    const float* __restrict__ bias, float* __restrict__ out)
{
    extern __shared__ __align__(16) unsigned so[];
    unsigned* Ah = so;
    unsigned* Al = so + 4608;
    unsigned* Bh = so + 9216;
    unsigned* Bl = so + 13824;

    const unsigned sbase = (unsigned)__cvta_generic_to_shared(so);
    const int t = threadIdx.x, lane = t & 31, warp = t >> 5;
    const int g = lane >> 2, tg = lane & 3;
    const int rr = lane & 7, tl = lane >> 3;
    const int m0 = blockIdx.x * 128;
    const int n0 = blockIdx.y * 128;
    const int rb = (warp & 3) * 32;
    const int cbn = (warp >> 2) * 64;

    const unsigned aoff = ((rb + rr + (tl & 1) * 8) * AS + (tl >> 1) * 4) * 4;
    const unsigned boff = ((cbn + rr + ((tl >> 1) & 1) * 8) * AS + (tl & 1) * 4) * 4;

    for (int i = t; i < 1024; i += 256) {
        int r = i >> 3, j = (i & 7) * 4;
        *(float4*)(Ah + r * AS + j) = *(const float4*)(g_attn_hi + (size_t)(m0 + r) * 32 + j);
        *(float4*)(Al + r * AS + j) = *(const float4*)(g_attn_lo + (size_t)(m0 + r) * 32 + j);
        *(float4*)(Bh + r * AS + j) = *(const float4*)(g_woT_hi + (size_t)(n0 + r) * 32 + j);
        *(float4*)(Bl + r * AS + j) = *(const float4*)(g_woT_lo + (size_t)(n0 + r) * 32 + j);
    }
    __syncthreads();

    float c[2][8][4] = {};
    #pragma unroll
    for (int kt = 0; kt < 4; kt++) {
        const unsigned ko = kt * 32;
        unsigned ah[2][4], al[2][4];
        LDSM4(ah[0][0], ah[0][1], ah[0][2], ah[0][3], sbase + aoff + ko);
        LDSM4(ah[1][0], ah[1][1], ah[1][2], ah[1][3], sbase + aoff + 16 * AS * 4 + ko);
        LDSM4(al[0][0], al[0][1], al[0][2], al[0][3], sbase + 4608 * 4 + aoff + ko);
        LDSM4(al[1][0], al[1][1], al[1][2], al[1][3], sbase + 4608 * 4 + aoff + 16 * AS * 4 + ko);
        #pragma unroll
        for (int ntp = 0; ntp < 4; ntp++) {
            unsigned bh0, bh1, bh2, bh3, bl0, bl1, bl2, bl3;
            LDSM4(bh0, bh1, bh2, bh3, sbase + 9216 * 4 + boff + ntp * 16 * AS * 4 + ko);
            LDSM4(bl0, bl1, bl2, bl3, sbase + 13824 * 4 + boff + ntp * 16 * AS * 4 + ko);
            #pragma unroll
            for (int gm = 0; gm < 2; gm++) {
                MMA16816(c[gm][2 * ntp],     ah[gm][0], ah[gm][1], ah[gm][2], ah[gm][3], bh0, bh1);
                MMA16816(c[gm][2 * ntp],     ah[gm][0], ah[gm][1], ah[gm][2], ah[gm][3], bl0, bl1);
                MMA16816(c[gm][2 * ntp],     al[gm][0], al[gm][1], al[gm][2], al[gm][3], bh0, bh1);
                MMA16816(c[gm][2 * ntp + 1], ah[gm][0], ah[gm][1], ah[gm][2], ah[gm][3], bh2, bh3);
                MMA16816(c[gm][2 * ntp + 1], ah[gm][0], ah[gm][1], ah[gm][2], ah[gm][3], bl2, bl3);
                MMA16816(c[gm][2 * ntp + 1], al[gm][0], al[gm][1], al[gm][2], al[gm][3], bh2, bh3);
            }
        }
    }

    #pragma unroll
    for (int gm = 0; gm < 2; gm++) {
        int row = m0 + rb + 16 * gm + g;
        #pragma unroll
        for (int nt = 0; nt < 8; nt++) {
            int col = n0 + cbn + 8 * nt + 2 * tg;
            float b0 = bias[col], b1 = bias[col + 1];
            *(float2*)(out + (size_t)row * DOUT + col)       = make_float2(c[gm][nt][0] + b0, c[gm][nt][1] + b1);
            *(float2*)(out + (size_t)(row + 8) * DOUT + col) = make_float2(c[gm][nt][2] + b0, c[gm][nt][3] + b1);
        }
    }
}

// ---------------------------------------------------------------------------
extern "C" void kernel_launch(void* const* d_in, const int* in_sizes, int n_in,
                              void* d_out, int out_size)
{
    const float* x    = (const float*)d_in[0];
    const float* Wqkv = (const float*)d_in[1];
    const float* Wout = (const float*)d_in[2];
    const float* bout = (const float*)d_in[3];
    float* out = (float*)d_out;

    prep_all_kernel<<<2304, 256>>>(x, Wqkv, Wout);

    cudaFuncSetAttribute(qkv_mma_kernel, cudaFuncAttributeMaxDynamicSharedMemorySize, 102400);
    qkv_mma_kernel<<<TOK / 128, 512, 102400>>>();

    cudaFuncSetAttribute(attn_mma_kernel, cudaFuncAttributeMaxDynamicSharedMemorySize, 110592);
    attn_mma_kernel<<<dim3(NCHUNK, NB), 256, 110592>>>();

    merge_kernel<<<dim3(28, NB), 256>>>();

    cudaFuncSetAttribute(out_mma_kernel, cudaFuncAttributeMaxDynamicSharedMemorySize, 73728);
    out_mma_kernel<<<dim3(TOK / 128, DOUT / 128), 256, 73728>>>(bout, out);
}

// round 15
// speedup vs baseline: 1.2045x; 1.1095x over previous
#include <cuda_runtime.h>
#include <cuda_bf16.h>

#define SEQ   4096
#define NB    4
#define TOK   (NB * SEQ)
#define DIN   512
#define DH    64
#define DOUT  512
#define NCHUNK 144                      // split-j chunks per batch (Br=128)
#define SCALE_LOG2E 0.1803368801111f    // 0.125 * log2(e)

// ---------------------------------------------------------------------------
// Device scratch (allocation-free). bf16 pairs packed in u32 words along k.
// ---------------------------------------------------------------------------
__device__ unsigned g_x_hi[TOK * (DIN/2)];
__device__ unsigned g_x_lo[TOK * (DIN/2)];
__device__ unsigned g_wqkvT_hi[192 * (DIN/2)];
__device__ unsigned g_wqkvT_lo[192 * (DIN/2)];
__device__ unsigned g_woT_hi[DOUT * (DH/2)];
__device__ unsigned g_woT_lo[DOUT * (DH/2)];
__device__ unsigned g_q_hi[TOK * (DH/2)];
__device__ unsigned g_q_lo[TOK * (DH/2)];
__device__ unsigned g_k_hi[TOK * (DH/2)];
__device__ unsigned g_k_lo[TOK * (DH/2)];
__device__ unsigned g_v_hi[TOK * (DH/2)];           // row-major like K
__device__ unsigned g_v_lo[TOK * (DH/2)];
__device__ unsigned g_attn_hi[TOK * (DH/2)];
__device__ unsigned g_attn_lo[TOK * (DH/2)];
__device__ float g_part_o[NB * NCHUNK * 128 * 64];  // unnormalized partial O
__device__ float g_part_m[NB * NCHUNK * 128];       // log2-domain row max
__device__ float g_part_l[NB * NCHUNK * 128];       // row sum

// ---------------------------------------------------------------------------
__device__ __forceinline__ void split2(float x0, float x1, unsigned &h, unsigned &l) {
    __nv_bfloat162 hh = __floats2bfloat162_rn(x0, x1);
    h = *reinterpret_cast<unsigned*>(&hh);
    float r0 = x0 - __bfloat162float(hh.x);
    float r1 = x1 - __bfloat162float(hh.y);
    __nv_bfloat162 ll = __floats2bfloat162_rn(r0, r1);
    l = *reinterpret_cast<unsigned*>(&ll);
}

#define MMA16816(c, a0, a1, a2, a3, b0, b1)                                   \
    asm volatile(                                                             \
        "mma.sync.aligned.m16n8k16.row.col.f32.bf16.bf16.f32 "                \
        "{%0,%1,%2,%3}, {%4,%5,%6,%7}, {%8,%9}, {%0,%1,%2,%3};\n"             \
        : "+f"((c)[0]), "+f"((c)[1]), "+f"((c)[2]), "+f"((c)[3])              \
        : "r"(a0), "r"(a1), "r"(a2), "r"(a3), "r"(b0), "r"(b1))

#define LDSM4(d0, d1, d2, d3, a)                                              \
    asm volatile("ldmatrix.sync.aligned.m8n8.x4.shared.b16 {%0,%1,%2,%3}, [%4];" \
        : "=r"(d0), "=r"(d1), "=r"(d2), "=r"(d3) : "r"(a))

#define LDSM4T(d0, d1, d2, d3, a)                                             \
    asm volatile("ldmatrix.sync.aligned.m8n8.x4.trans.shared.b16 {%0,%1,%2,%3}, [%4];" \
        : "=r"(d0), "=r"(d1), "=r"(d2), "=r"(d3) : "r"(a))

__device__ __forceinline__ void cpa16(unsigned dst, const void* src) {
    asm volatile("cp.async.cg.shared.global [%0], [%1], 16;\n" :: "r"(dst), "l"(src));
}
#define CP_COMMIT asm volatile("cp.async.commit_group;\n" ::: "memory")
#define CP_WAIT0  asm volatile("cp.async.wait_group 0;\n" ::: "memory")

// ---------------------------------------------------------------------------
// Fused prep kernel: blocks [0,2048) split x; [2048,2240) W_qkv^T; [2240,2304) W_out^T.
// ---------------------------------------------------------------------------
__global__ __launch_bounds__(256) void prep_all_kernel(
    const float* __restrict__ x, const float* __restrict__ wqkv,
    const float* __restrict__ wout)
{
    const int bx = blockIdx.x;
    if (bx < 2048) {
        int i0 = bx * 1024 + threadIdx.x;
        #pragma unroll
        for (int it = 0; it < 4; it++) {
            int idx = i0 + it * 256;
            float4 v = *(const float4*)(x + (size_t)idx * 4);
            unsigned h0, l0, h1, l1;
            split2(v.x, v.y, h0, l0);
            split2(v.z, v.w, h1, l1);
            g_x_hi[2 * idx] = h0; g_x_hi[2 * idx + 1] = h1;
            g_x_lo[2 * idx] = l0; g_x_lo[2 * idx + 1] = l1;
        }
    } else if (bx < 2240) {
        int n = bx - 2048, kw = threadIdx.x;
        float a = wqkv[(size_t)(2 * kw) * 192 + n];
        float b = wqkv[(size_t)(2 * kw + 1) * 192 + n];
        unsigned h, l; split2(a, b, h, l);
        g_wqkvT_hi[n * 256 + kw] = h; g_wqkvT_lo[n * 256 + kw] = l;
    } else {
        int idx = (bx - 2240) * 256 + threadIdx.x;
        int n = idx >> 5, kw = idx & 31;
        float a = wout[(size_t)(2 * kw) * DOUT + n];
        float b = wout[(size_t)(2 * kw + 1) * DOUT + n];
        unsigned h, l; split2(a, b, h, l);
        g_woT_hi[n * 32 + kw] = h; g_woT_lo[n * 32 + kw] = l;
    }
}

// ---------------------------------------------------------------------------
// K1: qkv GEMM, single-wave fat tile. 512 thr (16 warps: 4m x 4n), CTA tile
// M=128 x N=192, k-chunks 32, cp.async TWO-stage, ldmatrix. grid = 128 CTAs.
// Stage (12800 words): XH 0, XL 2560, WH 5120, WL 8960.
// ---------------------------------------------------------------------------
#define QS 20

__global__ __launch_bounds__(512) void qkv_mma_kernel() {
    extern __shared__ __align__(16) unsigned sq[];
    const unsigned sbase = (unsigned)__cvta_generic_to_shared(sq);
    const int t = threadIdx.x, lane = t & 31, warp = t >> 5;
    const int g = lane >> 2, tg = lane & 3;
    const int rr = lane & 7, tl = lane >> 3;
    const int m0 = blockIdx.x * 128;
    const int rb = (warp & 3) * 32;    // m-warp: 32 rows
    const int cb = (warp >> 2) * 48;   // n-warp: 48 cols

    const unsigned aoff = ((rb + rr + (tl & 1) * 8) * QS + (tl >> 1) * 4) * 4;
    const unsigned boff = ((cb + rr + ((tl >> 1) & 1) * 8) * QS + (tl & 1) * 4) * 4;

    auto prefetch = [&](int kc, int st) {
        unsigned sb = sbase + st * 12800 * 4;
        {   // X hi/lo: 512 float4 each, 1 per thread
            int r = t >> 2, j = (t & 3) * 4;
            cpa16(sb + (r * QS + j) * 4,          g_x_hi + (size_t)(m0 + r) * 256 + kc * 16 + j);
            cpa16(sb + (2560 + r * QS + j) * 4,   g_x_lo + (size_t)(m0 + r) * 256 + kc * 16 + j);
        }
        #pragma unroll
        for (int i = 0; i < 2; i++) {
            int idx = t + i * 512;
            if (idx < 768) {
                int r = idx >> 2, j = (idx & 3) * 4;
                cpa16(sb + (5120 + r * QS + j) * 4,   g_wqkvT_hi + (size_t)r * 256 + kc * 16 + j);
                cpa16(sb + (8960 + r * QS + j) * 4,   g_wqkvT_lo + (size_t)r * 256 + kc * 16 + j);
            }
        }
        CP_COMMIT;
    };

    float c[2][6][4] = {};
    prefetch(0, 0);

    for (int kc = 0; kc < 16; kc++) {
        const int st = kc & 1;
        CP_WAIT0;
        __syncthreads();
        if (kc + 1 < 16) prefetch(kc + 1, st ^ 1);

        const unsigned Xb = sbase + st * 12800 * 4;

        #pragma unroll
        for (int kt = 0; kt < 2; kt++) {
            const unsigned ko = kt * 32;   // 8 words
            unsigned ah[2][4], al[2][4];
            LDSM4(ah[0][0], ah[0][1], ah[0][2], ah[0][3], Xb + aoff + ko);
            LDSM4(ah[1][0], ah[1][1], ah[1][2], ah[1][3], Xb + aoff + 16 * QS * 4 + ko);
            LDSM4(al[0][0], al[0][1], al[0][2], al[0][3], Xb + 2560 * 4 + aoff + ko);
            LDSM4(al[1][0], al[1][1], al[1][2], al[1][3], Xb + 2560 * 4 + aoff + 16 * QS * 4 + ko);
            #pragma unroll
            for (int ntp = 0; ntp < 3; ntp++) {
                unsigned bh0, bh1, bh2, bh3, bl0, bl1, bl2, bl3;
                LDSM4(bh0, bh1, bh2, bh3, Xb + 5120 * 4 + boff + ntp * 16 * QS * 4 + ko);
                LDSM4(bl0, bl1, bl2, bl3, Xb + 8960 * 4 + boff + ntp * 16 * QS * 4 + ko);
                #pragma unroll
                for (int gm = 0; gm < 2; gm++) {
                    MMA16816(c[gm][2 * ntp],     ah[gm][0], ah[gm][1], ah[gm][2], ah[gm][3], bh0, bh1);
                    MMA16816(c[gm][2 * ntp],     ah[gm][0], ah[gm][1], ah[gm][2], ah[gm][3], bl0, bl1);
                    MMA16816(c[gm][2 * ntp],     al[gm][0], al[gm][1], al[gm][2], al[gm][3], bh0, bh1);
                    MMA16816(c[gm][2 * ntp + 1], ah[gm][0], ah[gm][1], ah[gm][2], ah[gm][3], bh2, bh3);
                    MMA16816(c[gm][2 * ntp + 1], ah[gm][0], ah[gm][1], ah[gm][2], ah[gm][3], bl2, bl3);
                    MMA16816(c[gm][2 * ntp + 1], al[gm][0], al[gm][1], al[gm][2], al[gm][3], bh2, bh3);
                }
            }
        }
    }

    // Epilogue: every n8 tile lies wholly in Q ([0,64)), K ([64,128)) or V ([128,192)).
    #pragma unroll
    for (int gm = 0; gm < 2; gm++) {
        int row = m0 + rb + 16 * gm + g;
        #pragma unroll
        for (int nt = 0; nt < 6; nt++) {
            int gcol = cb + 8 * nt;
            unsigned *oh, *ol;
            float qs2;
            int wd;
            if (gcol < 64)       { oh = g_q_hi; ol = g_q_lo; qs2 = SCALE_LOG2E; wd = (gcol >> 1) + tg; }
            else if (gcol < 128) { oh = g_k_hi; ol = g_k_lo; qs2 = 1.0f; wd = ((gcol - 64) >> 1) + tg; }
            else                 { oh = g_v_hi; ol = g_v_lo; qs2 = 1.0f; wd = ((gcol - 128) >> 1) + tg; }
            unsigned h, l;
            split2(c[gm][nt][0] * qs2, c[gm][nt][1] * qs2, h, l);
            oh[(size_t)row * 32 + wd] = h; ol[(size_t)row * 32 + wd] = l;
            split2(c[gm][nt][2] * qs2, c[gm][nt][3] * qs2, h, l);
            oh[(size_t)(row + 8) * 32 + wd] = h; ol[(size_t)(row + 8) * 32 + wd] = l;
        }
    }
}

// ---------------------------------------------------------------------------
// K2: split-j causal flash attention. 256 thr (8 warps), Br=128, Bc=64,
// cp.async 2-stage, ldmatrix fragment loads; V via ldmatrix.trans (row-major).
// ---------------------------------------------------------------------------
#define AS 36

__global__ __launch_bounds__(256) void attn_mma_kernel() {
    extern __shared__ __align__(16) unsigned sa[];
    const unsigned sbase = (unsigned)__cvta_generic_to_shared(sa);
    const int t = threadIdx.x, lane = t & 31, warp = t >> 5;
    const int g = lane >> 2, tg = lane & 3;
    const int rr = lane & 7, tl = lane >> 3;
    const int b = blockIdx.y;
    const int cx = blockIdx.x;

    int gr = 0;
    while (cx >= 2 * (gr + 1) * (gr + 2)) gr++;
    const int u = cx - 2 * gr * (gr + 1);
    const int ib = 4 * gr + u / (gr + 1);
    const int ci = u % (gr + 1);
    const int nch = gr + 1;
    const int jbeg = ci * 8;
    const int jend = min(jbeg + 8, 2 * ib + 2);
    const int i0 = ib * 128;

    const unsigned aoffQ = ((16 * warp + rr + (tl & 1) * 8) * AS + (tl >> 1) * 4) * 4;
    const unsigned boffB = ((rr + ((tl >> 1) & 1) * 8) * AS + (tl & 1) * 4) * 4;
    const unsigned voffT = ((rr + (tl & 1) * 8) * AS + (tl >> 1) * 4) * 4;

    unsigned* Qh = sa;
    unsigned* Ql = sa + 4608;
    for (int i = t; i < 1024; i += 256) {
        int r = i >> 3, j = (i & 7) * 4;
        *(float4*)(Qh + r * AS + j) = *(const float4*)(g_q_hi + (size_t)(b * SEQ + i0 + r) * 32 + j);
        *(float4*)(Ql + r * AS + j) = *(const float4*)(g_q_lo + (size_t)(b * SEQ + i0 + r) * 32 + j);
    }

    auto prefetch = [&](int jt, int st) {
        unsigned sb = sbase + (9216 + st * 9216) * 4;
        #pragma unroll
        for (int i = 0; i < 2; i++) {
            int idx = t + i * 256;
            int r = idx >> 3, j = idx & 7;
            cpa16(sb + (r * AS + 4 * j) * 4,          g_k_hi + (size_t)(b * SEQ + jt * 64 + r) * 32 + 4 * j);
            cpa16(sb + (2304 + r * AS + 4 * j) * 4,   g_k_lo + (size_t)(b * SEQ + jt * 64 + r) * 32 + 4 * j);
            cpa16(sb + (4608 + r * AS + 4 * j) * 4,   g_v_hi + (size_t)(b * SEQ + jt * 64 + r) * 32 + 4 * j);
            cpa16(sb + (6912 + r * AS + 4 * j) * 4,   g_v_lo + (size_t)(b * SEQ + jt * 64 + r) * 32 + 4 * j);
        }
        CP_COMMIT;
    };

    float o[8][4] = {};
    float mrow[2] = {-1e30f, -1e30f};
    float lrow[2] = {0.f, 0.f};

    prefetch(jbeg, 0);

    for (int jt = jbeg; jt < jend; jt++) {
        const int st = (jt - jbeg) & 1;
        CP_WAIT0;
        __syncthreads();
        if (jt + 1 < jend) prefetch(jt + 1, st ^ 1);

        const unsigned KVb = sbase + (9216 + st * 9216) * 4;

        float c[8][4] = {};
        #pragma unroll
        for (int kt = 0; kt < 4; kt++) {
            const unsigned ko = kt * 32;
            unsigned ah0, ah1, ah2, ah3, al0, al1, al2, al3;
            LDSM4(ah0, ah1, ah2, ah3, sbase + aoffQ + ko);
            LDSM4(al0, al1, al2, al3, sbase + 4608 * 4 + aoffQ + ko);
            #pragma unroll
            for (int ntp = 0; ntp < 4; ntp++) {
                unsigned bh0, bh1, bh2, bh3, bl0, bl1, bl2, bl3;
                LDSM4(bh0, bh1, bh2, bh3, KVb + boffB + ntp * 16 * AS * 4 + ko);
                LDSM4(bl0, bl1, bl2, bl3, KVb + 2304 * 4 + boffB + ntp * 16 * AS * 4 + ko);
                MMA16816(c[2 * ntp],     ah0, ah1, ah2, ah3, bh0, bh1);
                MMA16816(c[2 * ntp],     ah0, ah1, ah2, ah3, bl0, bl1);
                MMA16816(c[2 * ntp],     al0, al1, al2, al3, bh0, bh1);
                MMA16816(c[2 * ntp + 1], ah0, ah1, ah2, ah3, bh2, bh3);
                MMA16816(c[2 * ntp + 1], ah0, ah1, ah2, ah3, bl2, bl3);
                MMA16816(c[2 * ntp + 1], al0, al1, al2, al3, bh2, bh3);
            }
        }

        if (jt >= 2 * ib) {
            #pragma unroll
            for (int nt = 0; nt < 8; nt++) {
                #pragma unroll
                for (int e = 0; e < 4; e++) {
                    int row = i0 + 16 * warp + g + (e >= 2 ? 8 : 0);
                    int col = jt * 64 + 8 * nt + 2 * tg + (e & 1);
                    if (col > row) c[nt][e] = -1e30f;
                }
            }
        }

        float mx0 = -1e30f, mx1 = -1e30f;
        #pragma unroll
        for (int nt = 0; nt < 8; nt++) {
            mx0 = fmaxf(mx0, fmaxf(c[nt][0], c[nt][1]));
            mx1 = fmaxf(mx1, fmaxf(c[nt][2], c[nt][3]));
        }
        mx0 = fmaxf(mx0, __shfl_xor_sync(0xffffffffu, mx0, 1));
        mx0 = fmaxf(mx0, __shfl_xor_sync(0xffffffffu, mx0, 2));
        mx1 = fmaxf(mx1, __shfl_xor_sync(0xffffffffu, mx1, 1));
        mx1 = fmaxf(mx1, __shfl_xor_sync(0xffffffffu, mx1, 2));
        float mn0 = fmaxf(mrow[0], mx0), mn1 = fmaxf(mrow[1], mx1);
        float a0 = exp2f(mrow[0] - mn0), a1 = exp2f(mrow[1] - mn1);
        mrow[0] = mn0; mrow[1] = mn1;

        float s0 = 0.f, s1 = 0.f;
        #pragma unroll
        for (int nt = 0; nt < 8; nt++) {
            c[nt][0] = exp2f(c[nt][0] - mn0); s0 += c[nt][0];
            c[nt][1] = exp2f(c[nt][1] - mn0); s0 += c[nt][1];
            c[nt][2] = exp2f(c[nt][2] - mn1); s1 += c[nt][2];
            c[nt][3] = exp2f(c[nt][3] - mn1); s1 += c[nt][3];
        }
        s0 += __shfl_xor_sync(0xffffffffu, s0, 1);
        s0 += __shfl_xor_sync(0xffffffffu, s0, 2);
        s1 += __shfl_xor_sync(0xffffffffu, s1, 1);
        s1 += __shfl_xor_sync(0xffffffffu, s1, 2);
        lrow[0] = lrow[0] * a0 + s0;
        lrow[1] = lrow[1] * a1 + s1;
        #pragma unroll
        for (int nt = 0; nt < 8; nt++) {
            o[nt][0] *= a0; o[nt][1] *= a0; o[nt][2] *= a1; o[nt][3] *= a1;
        }

        #pragma unroll
        for (int kt = 0; kt < 4; kt++) {
            unsigned ah0, al0, ah1, al1, ah2, al2, ah3, al3;
            split2(c[2 * kt][0],     c[2 * kt][1],     ah0, al0);
            split2(c[2 * kt][2],     c[2 * kt][3],     ah1, al1);
            split2(c[2 * kt + 1][0], c[2 * kt + 1][1], ah2, al2);
            split2(c[2 * kt + 1][2], c[2 * kt + 1][3], ah3, al3);
            const unsigned kvo = kt * 16 * AS * 4;
            #pragma unroll
            for (int ntp = 0; ntp < 4; ntp++) {
                unsigned bh0, bh1, bh2, bh3, bl0, bl1, bl2, bl3;
                LDSM4T(bh0, bh1, bh2, bh3, KVb + 4608 * 4 + voffT + kvo + ntp * 32);
                LDSM4T(bl0, bl1, bl2, bl3, KVb + 6912 * 4 + voffT + kvo + ntp * 32);
                MMA16816(o[2 * ntp],     ah0, ah1, ah2, ah3, bh0, bh1);
                MMA16816(o[2 * ntp],     ah0, ah1, ah2, ah3, bl0, bl1);
                MMA16816(o[2 * ntp],     al0, al1, al2, al3, bh0, bh1);
                MMA16816(o[2 * ntp + 1], ah0, ah1, ah2, ah3, bh2, bh3);
                MMA16816(o[2 * ntp + 1], ah0, ah1, ah2, ah3, bl2, bl3);
                MMA16816(o[2 * ntp + 1], al0, al1, al2, al3, bh2, bh3);
            }
        }
    }

    if (nch == 1) {
        float inv0 = 1.0f / lrow[0], inv1 = 1.0f / lrow[1];
        const int tok = b * SEQ + i0 + 16 * warp + g;
        #pragma unroll
        for (int nt = 0; nt < 8; nt++) {
            unsigned h, l;
            split2(o[nt][0] * inv0, o[nt][1] * inv0, h, l);
            g_attn_hi[(size_t)tok * 32 + 4 * nt + tg] = h;
            g_attn_lo[(size_t)tok * 32 + 4 * nt + tg] = l;
            split2(o[nt][2] * inv1, o[nt][3] * inv1, h, l);
            g_attn_hi[(size_t)(tok + 8) * 32 + 4 * nt + tg] = h;
            g_attn_lo[(size_t)(tok + 8) * 32 + 4 * nt + tg] = l;
        }
    } else {
        const int pb = b * NCHUNK + cx;
        const int r0 = 16 * warp + g;
        #pragma unroll
        for (int nt = 0; nt < 8; nt++) {
            int col = 8 * nt + 2 * tg;
            *(float2*)&g_part_o[((size_t)pb * 128 + r0) * 64 + col]     = make_float2(o[nt][0], o[nt][1]);
            *(float2*)&g_part_o[((size_t)pb * 128 + r0 + 8) * 64 + col] = make_float2(o[nt][2], o[nt][3]);
        }
        if (tg == 0) {
            g_part_m[pb * 128 + r0] = mrow[0];     g_part_l[pb * 128 + r0] = lrow[0];
            g_part_m[pb * 128 + r0 + 8] = mrow[1]; g_part_l[pb * 128 + r0 + 8] = lrow[1];
        }
    }
}

// ---------------------------------------------------------------------------
// K2b: merge split-j partials. ONE WARP PER ROW for full parallelism:
// grid (448, NB): blockIdx.x = (ib-4)*16 + rblk, 8 rows (warps) per CTA.
// Lane holds cols (2*lane, 2*lane+1) -> coalesced 256B loads per chunk.
// ---------------------------------------------------------------------------
__global__ __launch_bounds__(256) void merge_kernel() {
    const int ibi = blockIdx.x >> 4;          // 0..27
    const int rblk = blockIdx.x & 15;         // 0..15
    const int ib = 4 + ibi;
    const int b = blockIdx.y;
    const int gr = ib >> 2;
    const int nch = gr + 1;
    const int cx0 = 2 * gr * (gr + 1) + (ib - 4 * gr) * (gr + 1);

    const int warp = threadIdx.x >> 5, lane = threadIdx.x & 31;
    const int r = rblk * 8 + warp;            // 0..127

    float mc[8], lc[8], wv[8];
    float mstar = -1e30f;
    #pragma unroll 4
    for (int c = 0; c < nch; c++) {
        mc[c] = g_part_m[(b * NCHUNK + cx0 + c) * 128 + r];
        lc[c] = g_part_l[(b * NCHUNK + cx0 + c) * 128 + r];
        mstar = fmaxf(mstar, mc[c]);
    }
    float lsum = 0.f;
    #pragma unroll 4
    for (int c = 0; c < nch; c++) { wv[c] = exp2f(mc[c] - mstar); lsum += wv[c] * lc[c]; }
    const float inv = 1.0f / lsum;

    float a0 = 0.f, a1 = 0.f;
    #pragma unroll 4
    for (int c = 0; c < nch; c++) {
        float2 v = *(const float2*)&g_part_o[((size_t)((b * NCHUNK + cx0 + c) * 128 + r)) * 64 + 2 * lane];
        a0 += wv[c] * v.x; a1 += wv[c] * v.y;
    }
    unsigned h, l; split2(a0 * inv, a1 * inv, h, l);
    const int tok = b * SEQ + ib * 128 + r;
    g_attn_hi[(size_t)tok * 32 + lane] = h;
    g_attn_lo[(size_t)tok * 32 + lane] = l;
}

// ---------------------------------------------------------------------------
// K3: out = attn @ W_out + b_out. 256 thr, tile 128x128, ldmatrix loads.
// ---------------------------------------------------------------------------
__global__ __launch_bounds__(256) void out_mma_kernel(
    const float* __restrict__ bias, float* __restrict__ out)
{
    extern __shared__ __align__(16) unsigned so[];
    unsigned* Ah = so;
    unsigned* Al = so + 4608;
    unsigned* Bh = so + 9216;
    unsigned* Bl = so + 13824;

    const unsigned sbase = (unsigned)__cvta_generic_to_shared(so);
    const int t = threadIdx.x, lane = t & 31, warp = t >> 5;
    const int g = lane >> 2, tg = lane & 3;
    const int rr = lane & 7, tl = lane >> 3;
    const int m0 = blockIdx.x * 128;
    const int n0 = blockIdx.y * 128;
    const int rb = (warp & 3) * 32;
    const int cbn = (warp >> 2) * 64;

    const unsigned aoff = ((rb + rr + (tl & 1) * 8) * AS + (tl >> 1) * 4) * 4;
    const unsigned boff = ((cbn + rr + ((tl >> 1) & 1) * 8) * AS + (tl & 1) * 4) * 4;

    for (int i = t; i < 1024; i += 256) {
        int r = i >> 3, j = (i & 7) * 4;
        *(float4*)(Ah + r * AS + j) = *(const float4*)(g_attn_hi + (size_t)(m0 + r) * 32 + j);
        *(float4*)(Al + r * AS + j) = *(const float4*)(g_attn_lo + (size_t)(m0 + r) * 32 + j);
        *(float4*)(Bh + r * AS + j) = *(const float4*)(g_woT_hi + (size_t)(n0 + r) * 32 + j);
        *(float4*)(Bl + r * AS + j) = *(const float4*)(g_woT_lo + (size_t)(n0 + r) * 32 + j);
    }
    __syncthreads();

    float c[2][8][4] = {};
    #pragma unroll
    for (int kt = 0; kt < 4; kt++) {
        const unsigned ko = kt * 32;
        unsigned ah[2][4], al[2][4];
        LDSM4(ah[0][0], ah[0][1], ah[0][2], ah[0][3], sbase + aoff + ko);
        LDSM4(ah[1][0], ah[1][1], ah[1][2], ah[1][3], sbase + aoff + 16 * AS * 4 + ko);
        LDSM4(al[0][0], al[0][1], al[0][2], al[0][3], sbase + 4608 * 4 + aoff + ko);
        LDSM4(al[1][0], al[1][1], al[1][2], al[1][3], sbase + 4608 * 4 + aoff + 16 * AS * 4 + ko);
        #pragma unroll
        for (int ntp = 0; ntp < 4; ntp++) {
            unsigned bh0, bh1, bh2, bh3, bl0, bl1, bl2, bl3;
            LDSM4(bh0, bh1, bh2, bh3, sbase + 9216 * 4 + boff + ntp * 16 * AS * 4 + ko);
            LDSM4(bl0, bl1, bl2, bl3, sbase + 13824 * 4 + boff + ntp * 16 * AS * 4 + ko);
            #pragma unroll
            for (int gm = 0; gm < 2; gm++) {
                MMA16816(c[gm][2 * ntp],     ah[gm][0], ah[gm][1], ah[gm][2], ah[gm][3], bh0, bh1);
                MMA16816(c[gm][2 * ntp],     ah[gm][0], ah[gm][1], ah[gm][2], ah[gm][3], bl0, bl1);
                MMA16816(c[gm][2 * ntp],     al[gm][0], al[gm][1], al[gm][2], al[gm][3], bh0, bh1);
                MMA16816(c[gm][2 * ntp + 1], ah[gm][0], ah[gm][1], ah[gm][2], ah[gm][3], bh2, bh3);
                MMA16816(c[gm][2 * ntp + 1], ah[gm][0], ah[gm][1], ah[gm][2], ah[gm][3], bl2, bl3);
                MMA16816(c[gm][2 * ntp + 1], al[gm][0], al[gm][1], al[gm][2], al[gm][3], bh2, bh3);
            }
        }
    }

    #pragma unroll
    for (int gm = 0; gm < 2; gm++) {
        int row = m0 + rb + 16 * gm + g;
        #pragma unroll
        for (int nt = 0; nt < 8; nt++) {
            int col = n0 + cbn + 8 * nt + 2 * tg;
            float b0 = bias[col], b1 = bias[col + 1];
            *(float2*)(out + (size_t)row * DOUT + col)       = make_float2(c[gm][nt][0] + b0, c[gm][nt][1] + b1);
            *(float2*)(out + (size_t)(row + 8) * DOUT + col) = make_float2(c[gm][nt][2] + b0, c[gm][nt][3] + b1);
        }
    }
}

// ---------------------------------------------------------------------------
extern "C" void kernel_launch(void* const* d_in, const int* in_sizes, int n_in,
                              void* d_out, int out_size)
{
    const float* x    = (const float*)d_in[0];
    const float* Wqkv = (const float*)d_in[1];
    const float* Wout = (const float*)d_in[2];
    const float* bout = (const float*)d_in[3];
    float* out = (float*)d_out;

    prep_all_kernel<<<2304, 256>>>(x, Wqkv, Wout);

    cudaFuncSetAttribute(qkv_mma_kernel, cudaFuncAttributeMaxDynamicSharedMemorySize, 102400);
    qkv_mma_kernel<<<TOK / 128, 512, 102400>>>();

    cudaFuncSetAttribute(attn_mma_kernel, cudaFuncAttributeMaxDynamicSharedMemorySize, 110592);
    attn_mma_kernel<<<dim3(NCHUNK, NB), 256, 110592>>>();

    merge_kernel<<<dim3(448, NB), 256>>>();

    cudaFuncSetAttribute(out_mma_kernel, cudaFuncAttributeMaxDynamicSharedMemorySize, 73728);
    out_mma_kernel<<<dim3(TOK / 128, DOUT / 128), 256, 73728>>>(bout, out);
}